// round 4
// baseline (speedup 1.0000x reference)
#include <cuda_runtime.h>
#include <cuda_bf16.h>
#include <cstdint>

#define B_   2048
#define F_   128
#define E_   128
#define KH   8
#define O_   64
#define FOLD 0.0625f     // (alpha-1) * d_k^-0.5 folded into C
#define NIT  12          // Newton iterations

// ---------------- device scratch (static, allowed) ----------------
__device__ __align__(16) __nv_bfloat16 g_Ch[4 * 128 * 128];  // [hp][m][x]
__device__ __align__(16) __nv_bfloat16 g_Cl[4 * 128 * 128];

// smem: Xh tile [128][272B] + Xl tile [128][272B]
#define XSTRIDE 272
#define XLOFF   (128 * XSTRIDE)
#define SM_TOTAL (2 * 128 * XSTRIDE)   // 69632 B

__device__ __forceinline__ uint32_t smem_u32(const void* p) {
    uint32_t a;
    asm("{ .reg .u64 t; cvta.to.shared.u64 t, %1; cvt.u32.u64 %0, t; }" : "=r"(a) : "l"(p));
    return a;
}

__device__ __forceinline__ void mma_bf16(float* d,
                                         uint32_t a0, uint32_t a1, uint32_t a2, uint32_t a3,
                                         uint32_t b0, uint32_t b1) {
    asm volatile("mma.sync.aligned.m16n8k16.row.col.f32.bf16.bf16.f32 "
                 "{%0,%1,%2,%3}, {%4,%5,%6,%7}, {%8,%9}, {%0,%1,%2,%3};"
                 : "+f"(d[0]), "+f"(d[1]), "+f"(d[2]), "+f"(d[3])
                 : "r"(a0), "r"(a1), "r"(a2), "r"(a3), "r"(b0), "r"(b1));
}

__device__ __forceinline__ void ldmx4(uint32_t& b0, uint32_t& b1, uint32_t& b2, uint32_t& b3,
                                      uint32_t addr) {
    asm volatile("ldmatrix.sync.aligned.m8n8.x4.shared.b16 {%0,%1,%2,%3}, [%4];"
                 : "=r"(b0), "=r"(b1), "=r"(b2), "=r"(b3) : "r"(addr));
}

__device__ __forceinline__ uint32_t pack_bf16hi(float a, float b) {
    __nv_bfloat162 h{__float2bfloat16(a), __float2bfloat16(b)};
    return *(uint32_t*)&h;
}

// ---------------------------------------------------------------------------
// prep: C[hp][m][x] = FOLD * sum_y W[k][x][y]*Q[k][o][y], bf16 hi/lo split
// grid = 64 blocks (k, x-chunk of 16), 256 threads
// ---------------------------------------------------------------------------
#define QS_STRIDE 65
__global__ __launch_bounds__(256)
void prep_kernel(const float* __restrict__ W, const float* __restrict__ Q) {
    __shared__ float qs[64 * QS_STRIDE];   // [o][y], padded
    __shared__ float ws[16 * 64];          // [xl][y]
    const int tid = threadIdx.x;
    const int k   = blockIdx.x >> 3;
    const int x0  = (blockIdx.x & 7) * 16;

    for (int i = tid; i < 4096; i += 256)
        qs[(i >> 6) * QS_STRIDE + (i & 63)] = Q[k * 4096 + i];
    for (int i = tid; i < 1024; i += 256)
        ws[i] = W[(k * 128 + x0) * 64 + i];
    __syncthreads();

    const int hp = k >> 1;
    const int mb = (k & 1) * 64;
#pragma unroll
    for (int j = 0; j < 4; j++) {
        int xo = tid + j * 256;
        int xl = xo >> 6, o = xo & 63;
        const float* wr = ws + xl * 64;
        const float* qr = qs + o * QS_STRIDE;
        float acc = 0.0f;
#pragma unroll
        for (int y = 0; y < 64; y++) acc = fmaf(wr[y], qr[y], acc);
        acc *= FOLD;
        __nv_bfloat16 h = __float2bfloat16(acc);
        int idx = (hp * 128 + mb + o) * 128 + x0 + xl;
        g_Ch[idx] = h;
        g_Cl[idx] = __float2bfloat16(acc - __bfloat162float(h));
    }
}

// ---------------------------------------------------------------------------
// main: fused fp32->bf16 split staging + HMMA 3-term GEMM + entmax + values
// one CTA per (b, head-pair); 256 threads (8 warps, warp = m16 x n128 strip)
// ---------------------------------------------------------------------------
__global__ __launch_bounds__(256, 2)
void main_kernel(const float* __restrict__ Xg, const float* __restrict__ Vg,
                 float* __restrict__ out) {
    extern __shared__ char smem[];
    const int tid  = threadIdx.x;
    const int wid  = tid >> 5;
    const int lane = tid & 31;
    const int b    = blockIdx.x >> 2;
    const int hp   = blockIdx.x & 3;
    const int mw   = wid * 16;

    // ---- stage X[b]: fp32 -> bf16 hi/lo directly into smem ----
    {
        const float4* Xb4 = (const float4*)(Xg + (size_t)b * F_ * E_);
#pragma unroll
        for (int i = tid; i < 4096; i += 256) {
            int row = i >> 5, c = i & 31;
            float4 v = Xb4[i];
            uint2 hi, lo;
            __nv_bfloat16 h0 = __float2bfloat16(v.x), h1 = __float2bfloat16(v.y);
            __nv_bfloat16 h2 = __float2bfloat16(v.z), h3 = __float2bfloat16(v.w);
            __nv_bfloat162 p01{h0, h1}, p23{h2, h3};
            hi.x = *(uint32_t*)&p01; hi.y = *(uint32_t*)&p23;
            __nv_bfloat162 l01{__float2bfloat16(v.x - __bfloat162float(h0)),
                               __float2bfloat16(v.y - __bfloat162float(h1))};
            __nv_bfloat162 l23{__float2bfloat16(v.z - __bfloat162float(h2)),
                               __float2bfloat16(v.w - __bfloat162float(h3))};
            lo.x = *(uint32_t*)&l01; lo.y = *(uint32_t*)&l23;
            *(uint2*)(smem + row * XSTRIDE + c * 8)         = hi;
            *(uint2*)(smem + XLOFF + row * XSTRIDE + c * 8) = lo;
        }
    }
    __syncthreads();

    // ---- MMA mainloop: per (kt, nt) load Xh+Xl once, 3 MMAs into same acc ----
    float acc[16][4];
#pragma unroll
    for (int t = 0; t < 16; t++)
#pragma unroll
        for (int j = 0; j < 4; j++) acc[t][j] = 0.0f;

    const int g  = lane >> 2;       // row within m8
    const int tg = lane & 3;        // thread in group
    const int ln   = (lane & 7) + ((lane >> 4) << 3);
    const int lk8  = (lane >> 3) & 1;
    const uint32_t sbase = smem_u32(smem);

    const uint16_t* Ah = (const uint16_t*)(g_Ch + (hp * 128 + mw) * 128);
    const uint16_t* Al = (const uint16_t*)(g_Cl + (hp * 128 + mw) * 128);

#pragma unroll
    for (int kt = 0; kt < 8; kt++) {
        const int k0 = kt * 16 + 2 * tg;
        uint32_t a0 = *(const uint32_t*)(Ah + (g)     * 128 + k0);
        uint32_t a1 = *(const uint32_t*)(Ah + (g + 8) * 128 + k0);
        uint32_t a2 = *(const uint32_t*)(Ah + (g)     * 128 + k0 + 8);
        uint32_t a3 = *(const uint32_t*)(Ah + (g + 8) * 128 + k0 + 8);
        uint32_t c0 = *(const uint32_t*)(Al + (g)     * 128 + k0);
        uint32_t c1 = *(const uint32_t*)(Al + (g + 8) * 128 + k0);
        uint32_t c2 = *(const uint32_t*)(Al + (g)     * 128 + k0 + 8);
        uint32_t c3 = *(const uint32_t*)(Al + (g + 8) * 128 + k0 + 8);
        uint32_t raddr = sbase + (uint32_t)(ln * XSTRIDE + (kt * 2 + lk8) * 16);
#pragma unroll
        for (int nt2 = 0; nt2 < 8; nt2++) {
            uint32_t roff = raddr + (uint32_t)(nt2 * 16 * XSTRIDE);
            uint32_t b0, b1, b2, b3, l0, l1, l2, l3;
            ldmx4(b0, b1, b2, b3, roff);
            ldmx4(l0, l1, l2, l3, roff + (uint32_t)XLOFF);
            mma_bf16(acc[2 * nt2],     a0, a1, a2, a3, b0, b1);
            mma_bf16(acc[2 * nt2 + 1], a0, a1, a2, a3, b2, b3);
            mma_bf16(acc[2 * nt2],     a0, a1, a2, a3, l0, l1);
            mma_bf16(acc[2 * nt2 + 1], a0, a1, a2, a3, l2, l3);
            mma_bf16(acc[2 * nt2],     c0, c1, c2, c3, b0, b1);
            mma_bf16(acc[2 * nt2 + 1], c0, c1, c2, c3, b2, b3);
        }
    }

    // ---- epilogue: entmax-1.5, fully warp-local ----
    float mA = acc[0][0], mB = acc[0][2];
#pragma unroll
    for (int t = 0; t < 16; t++) {
        mA = fmaxf(mA, fmaxf(acc[t][0], acc[t][1]));
        mB = fmaxf(mB, fmaxf(acc[t][2], acc[t][3]));
    }
    mA = fmaxf(mA, __shfl_xor_sync(0xffffffffu, mA, 1));
    mA = fmaxf(mA, __shfl_xor_sync(0xffffffffu, mA, 2));
    mB = fmaxf(mB, __shfl_xor_sync(0xffffffffu, mB, 1));
    mB = fmaxf(mB, __shfl_xor_sync(0xffffffffu, mB, 2));

    float tauA = mA - 1.0f, tauB = mB - 1.0f;

#pragma unroll 1
    for (int it = 0; it < NIT; it++) {
        float sA = 0.f, qA = 0.f, sB = 0.f, qB = 0.f;
#pragma unroll
        for (int t = 0; t < 16; t++) {
            float r0 = fmaxf(acc[t][0] - tauA, 0.f);
            float r1 = fmaxf(acc[t][1] - tauA, 0.f);
            float r2 = fmaxf(acc[t][2] - tauB, 0.f);
            float r3 = fmaxf(acc[t][3] - tauB, 0.f);
            qA = fmaf(r0, r0, qA); sA += r0;
            qA = fmaf(r1, r1, qA); sA += r1;
            qB = fmaf(r2, r2, qB); sB += r2;
            qB = fmaf(r3, r3, qB); sB += r3;
        }
        qA += __shfl_xor_sync(0xffffffffu, qA, 1);
        qA += __shfl_xor_sync(0xffffffffu, qA, 2);
        sA += __shfl_xor_sync(0xffffffffu, sA, 1);
        sA += __shfl_xor_sync(0xffffffffu, sA, 2);
        qB += __shfl_xor_sync(0xffffffffu, qB, 1);
        qB += __shfl_xor_sync(0xffffffffu, qB, 2);
        sB += __shfl_xor_sync(0xffffffffu, sB, 1);
        sB += __shfl_xor_sync(0xffffffffu, sB, 2);
        tauA += __fdividef(qA - 1.0f, 2.0f * sA);
        tauB += __fdividef(qB - 1.0f, 2.0f * sB);
    }

    float pA = 0.f, pB = 0.f;
#pragma unroll
    for (int t = 0; t < 16; t++) {
        float r0 = fmaxf(acc[t][0] - tauA, 0.f);
        float r1 = fmaxf(acc[t][1] - tauA, 0.f);
        float r2 = fmaxf(acc[t][2] - tauB, 0.f);
        float r3 = fmaxf(acc[t][3] - tauB, 0.f);
        acc[t][0] = r0 * r0; pA += acc[t][0];
        acc[t][1] = r1 * r1; pA += acc[t][1];
        acc[t][2] = r2 * r2; pB += acc[t][2];
        acc[t][3] = r3 * r3; pB += acc[t][3];
    }
    pA += __shfl_xor_sync(0xffffffffu, pA, 1);
    pA += __shfl_xor_sync(0xffffffffu, pA, 2);
    pB += __shfl_xor_sync(0xffffffffu, pB, 1);
    pB += __shfl_xor_sync(0xffffffffu, pB, 2);
    const float invA = __fdividef(1.0f, pA);
    const float invB = __fdividef(1.0f, pB);

    const int rowA = mw + g;            // 0..127
    const int rowB = rowA + 8;
    const int k  = hp * 2 + (rowA >> 6);
    const int oA = rowA & 63;
    const int oB = rowB & 63;
    const float* vA = Vg + (k * O_ + oA) * F_;
    const float* vB = Vg + (k * O_ + oB) * F_;
    float* outA = out + (((size_t)b * KH + k) * O_ + oA) * F_;
    float* outB = out + (((size_t)b * KH + k) * O_ + oB) * F_;

#pragma unroll
    for (int t = 0; t < 16; t++) {
        int col = t * 8 + 2 * tg;
        float2 va = *(const float2*)(vA + col);
        float2 vb = *(const float2*)(vB + col);
        float2 wa, wb;
        wa.x = acc[t][0] * invA * va.x;
        wa.y = acc[t][1] * invA * va.y;
        wb.x = acc[t][2] * invB * vb.x;
        wb.y = acc[t][3] * invB * vb.y;
        *(float2*)(outA + col) = wa;
        *(float2*)(outB + col) = wb;
    }
}

// ---------------------------------------------------------------------------
extern "C" void kernel_launch(void* const* d_in, const int* in_sizes, int n_in,
                              void* d_out, int out_size) {
    const float* x = (const float*)d_in[0];   // [2048,128,128]
    const float* w = (const float*)d_in[1];   // [8,128,64]
    const float* q = (const float*)d_in[2];   // [8,64,64]
    const float* v = (const float*)d_in[3];   // [8,64,128]
    float* out = (float*)d_out;               // [2048,8,64,128]

    cudaFuncSetAttribute(main_kernel, cudaFuncAttributeMaxDynamicSharedMemorySize, SM_TOTAL);

    prep_kernel<<<64, 256>>>(w, q);
    main_kernel<<<B_ * 4, 256, SM_TOTAL>>>(x, v, out);
}

// round 5
// speedup vs baseline: 1.6470x; 1.6470x over previous
#include <cuda_runtime.h>
#include <cuda_bf16.h>
#include <cstdint>

#define B_   2048
#define F_   128
#define E_   128
#define KH   8
#define O_   64
#define FOLD 0.0625f     // (alpha-1) * d_k^-0.5 folded into C
#define NIT  12          // Newton iterations

// ---------------- device scratch ----------------
// A in MMA-fragment order: [hp][wid][kt][reg(0..7: a0..a3 hi unused split)][lane] u32
__device__ __align__(16) uint32_t g_FH[4 * 8 * 8 * 8 * 32];   // 256 KB (hi)
__device__ __align__(16) uint32_t g_FL[4 * 8 * 8 * 8 * 32];   // 256 KB (lo)

// smem: Xh [128][272B] + Xl [128][272B]; reused as att[128][132] fp32 in epilogue
#define XSTRIDE 272
#define XLOFF   (128 * XSTRIDE)
#define ASTRIDE 132
#define SM_TOTAL (2 * 128 * XSTRIDE)   // 69632 B >= 128*132*4 = 67584

__device__ __forceinline__ uint32_t smem_u32(const void* p) {
    uint32_t a;
    asm("{ .reg .u64 t; cvta.to.shared.u64 t, %1; cvt.u32.u64 %0, t; }" : "=r"(a) : "l"(p));
    return a;
}

__device__ __forceinline__ void mma_bf16(float* d,
                                         uint32_t a0, uint32_t a1, uint32_t a2, uint32_t a3,
                                         uint32_t b0, uint32_t b1) {
    asm volatile("mma.sync.aligned.m16n8k16.row.col.f32.bf16.bf16.f32 "
                 "{%0,%1,%2,%3}, {%4,%5,%6,%7}, {%8,%9}, {%0,%1,%2,%3};"
                 : "+f"(d[0]), "+f"(d[1]), "+f"(d[2]), "+f"(d[3])
                 : "r"(a0), "r"(a1), "r"(a2), "r"(a3), "r"(b0), "r"(b1));
}

__device__ __forceinline__ void ldmx4(uint32_t& b0, uint32_t& b1, uint32_t& b2, uint32_t& b3,
                                      uint32_t addr) {
    asm volatile("ldmatrix.sync.aligned.m8n8.x4.shared.b16 {%0,%1,%2,%3}, [%4];"
                 : "=r"(b0), "=r"(b1), "=r"(b2), "=r"(b3) : "r"(addr));
}

// ---------------------------------------------------------------------------
// prep: C = FOLD * W*Q^T per head, bf16 hi/lo split, stored in fragment order
// grid = 64 blocks (k, x-chunk of 16), 256 threads
// ---------------------------------------------------------------------------
#define QS_STRIDE 65
__global__ __launch_bounds__(256)
void prep_kernel(const float* __restrict__ W, const float* __restrict__ Q) {
    __shared__ float qs[64 * QS_STRIDE];   // [o][y], padded
    __shared__ float ws[16 * 64];          // [xl][y]
    const int tid = threadIdx.x;
    const int k   = blockIdx.x >> 3;
    const int x0  = (blockIdx.x & 7) * 16;

    for (int i = tid; i < 4096; i += 256)
        qs[(i >> 6) * QS_STRIDE + (i & 63)] = Q[k * 4096 + i];
    for (int i = tid; i < 1024; i += 256)
        ws[i] = W[(k * 128 + x0) * 64 + i];
    __syncthreads();

    const int hp = k >> 1;
    const int mb = (k & 1) * 64;
#pragma unroll
    for (int j = 0; j < 4; j++) {
        int xo = tid + j * 256;
        int xl = xo >> 6, o = xo & 63;
        const float* wr = ws + xl * 64;
        const float* qr = qs + o * QS_STRIDE;
        float acc = 0.0f;
#pragma unroll
        for (int y = 0; y < 64; y++) acc = fmaf(wr[y], qr[y], acc);
        acc *= FOLD;
        __nv_bfloat16 h = __float2bfloat16(acc);
        __nv_bfloat16 l = __float2bfloat16(acc - __bfloat162float(h));

        // fragment-order indexing
        const int m   = mb + o;
        const int x   = x0 + xl;
        const int wid = m >> 4, g = m & 7, pA = (m >> 3) & 1;
        const int kt  = x >> 4, xr = x & 15;
        const int hi8 = (xr >> 3) & 1, tg = (xr >> 1) & 3, half = x & 1;
        const int r    = pA + 2 * hi8;
        const int lane = g * 4 + tg;
        const int idx2 = ((((hp * 8 + wid) * 8 + kt) * 8 + r) * 32 + lane) * 2 + half;
        ((__nv_bfloat16*)g_FH)[idx2] = h;
        ((__nv_bfloat16*)g_FL)[idx2] = l;
    }
}

// ---------------------------------------------------------------------------
// main: fused fp32->bf16 split staging + HMMA 3-term GEMM + entmax + values
// one CTA per (b, head-pair); 256 threads (8 warps, warp = m16 x n128 strip)
// ---------------------------------------------------------------------------
__global__ __launch_bounds__(256, 2)
void main_kernel(const float* __restrict__ Xg, const float* __restrict__ Vg,
                 float* __restrict__ out) {
    extern __shared__ char smem[];
    const int tid  = threadIdx.x;
    const int wid  = tid >> 5;
    const int lane = tid & 31;
    const int b    = blockIdx.x >> 2;
    const int hp   = blockIdx.x & 3;
    const int mw   = wid * 16;

    // ---- stage X[b]: fp32 -> bf16 hi/lo directly into smem ----
    {
        const float4* Xb4 = (const float4*)(Xg + (size_t)b * F_ * E_);
#pragma unroll
        for (int i = tid; i < 4096; i += 256) {
            int row = i >> 5, c = i & 31;
            float4 v = Xb4[i];
            uint2 hi, lo;
            __nv_bfloat16 h0 = __float2bfloat16(v.x), h1 = __float2bfloat16(v.y);
            __nv_bfloat16 h2 = __float2bfloat16(v.z), h3 = __float2bfloat16(v.w);
            __nv_bfloat162 p01{h0, h1}, p23{h2, h3};
            hi.x = *(uint32_t*)&p01; hi.y = *(uint32_t*)&p23;
            __nv_bfloat162 l01{__float2bfloat16(v.x - __bfloat162float(h0)),
                               __float2bfloat16(v.y - __bfloat162float(h1))};
            __nv_bfloat162 l23{__float2bfloat16(v.z - __bfloat162float(h2)),
                               __float2bfloat16(v.w - __bfloat162float(h3))};
            lo.x = *(uint32_t*)&l01; lo.y = *(uint32_t*)&l23;
            *(uint2*)(smem + row * XSTRIDE + c * 8)         = hi;
            *(uint2*)(smem + XLOFF + row * XSTRIDE + c * 8) = lo;
        }
    }
    __syncthreads();

    // ---- MMA mainloop ----
    float acc[16][4];
#pragma unroll
    for (int t = 0; t < 16; t++)
#pragma unroll
        for (int j = 0; j < 4; j++) acc[t][j] = 0.0f;

    const int g  = lane >> 2;
    const int tg = lane & 3;
    const int ln  = (lane & 7) + ((lane >> 4) << 3);
    const int lk8 = (lane >> 3) & 1;
    const uint32_t sbase = smem_u32(smem);

    const uint32_t* FHw = g_FH + (hp * 8 + wid) * (8 * 8 * 32) + lane;
    const uint32_t* FLw = g_FL + (hp * 8 + wid) * (8 * 8 * 32) + lane;

#pragma unroll
    for (int kt = 0; kt < 8; kt++) {
        const uint32_t* FH = FHw + kt * 256;
        const uint32_t* FL = FLw + kt * 256;
        uint32_t a0 = FH[0], a1 = FH[32], a2 = FH[64], a3 = FH[96];
        uint32_t c0 = FL[0], c1 = FL[32], c2 = FL[64], c3 = FL[96];
        uint32_t raddr = sbase + (uint32_t)(ln * XSTRIDE + (kt * 2 + lk8) * 16);
#pragma unroll
        for (int nt2 = 0; nt2 < 8; nt2++) {
            uint32_t roff = raddr + (uint32_t)(nt2 * 16 * XSTRIDE);
            uint32_t b0, b1, b2, b3, l0, l1, l2, l3;
            ldmx4(b0, b1, b2, b3, roff);
            ldmx4(l0, l1, l2, l3, roff + (uint32_t)XLOFF);
            mma_bf16(acc[2 * nt2],     a0, a1, a2, a3, b0, b1);
            mma_bf16(acc[2 * nt2 + 1], a0, a1, a2, a3, b2, b3);
            mma_bf16(acc[2 * nt2],     a0, a1, a2, a3, l0, l1);
            mma_bf16(acc[2 * nt2 + 1], a0, a1, a2, a3, l2, l3);
            mma_bf16(acc[2 * nt2],     c0, c1, c2, c3, b0, b1);
            mma_bf16(acc[2 * nt2 + 1], c0, c1, c2, c3, b2, b3);
        }
    }

    // ---- entmax-1.5, fully warp-local ----
    float mA = acc[0][0], mB = acc[0][2];
#pragma unroll
    for (int t = 0; t < 16; t++) {
        mA = fmaxf(mA, fmaxf(acc[t][0], acc[t][1]));
        mB = fmaxf(mB, fmaxf(acc[t][2], acc[t][3]));
    }
    mA = fmaxf(mA, __shfl_xor_sync(0xffffffffu, mA, 1));
    mA = fmaxf(mA, __shfl_xor_sync(0xffffffffu, mA, 2));
    mB = fmaxf(mB, __shfl_xor_sync(0xffffffffu, mB, 1));
    mB = fmaxf(mB, __shfl_xor_sync(0xffffffffu, mB, 2));

    float tauA = mA - 1.0f, tauB = mB - 1.0f;

#pragma unroll 1
    for (int it = 0; it < NIT; it++) {
        float sA = 0.f, qA = 0.f, sB = 0.f, qB = 0.f;
#pragma unroll
        for (int t = 0; t < 16; t++) {
            float r0 = fmaxf(acc[t][0] - tauA, 0.f);
            float r1 = fmaxf(acc[t][1] - tauA, 0.f);
            float r2 = fmaxf(acc[t][2] - tauB, 0.f);
            float r3 = fmaxf(acc[t][3] - tauB, 0.f);
            qA = fmaf(r0, r0, qA); sA += r0;
            qA = fmaf(r1, r1, qA); sA += r1;
            qB = fmaf(r2, r2, qB); sB += r2;
            qB = fmaf(r3, r3, qB); sB += r3;
        }
        qA += __shfl_xor_sync(0xffffffffu, qA, 1);
        qA += __shfl_xor_sync(0xffffffffu, qA, 2);
        sA += __shfl_xor_sync(0xffffffffu, sA, 1);
        sA += __shfl_xor_sync(0xffffffffu, sA, 2);
        qB += __shfl_xor_sync(0xffffffffu, qB, 1);
        qB += __shfl_xor_sync(0xffffffffu, qB, 2);
        sB += __shfl_xor_sync(0xffffffffu, sB, 1);
        sB += __shfl_xor_sync(0xffffffffu, sB, 2);
        tauA += __fdividef(qA - 1.0f, 2.0f * sA);
        tauB += __fdividef(qB - 1.0f, 2.0f * sB);
    }

    float pA = 0.f, pB = 0.f;
#pragma unroll
    for (int t = 0; t < 16; t++) {
        float r0 = fmaxf(acc[t][0] - tauA, 0.f);
        float r1 = fmaxf(acc[t][1] - tauA, 0.f);
        float r2 = fmaxf(acc[t][2] - tauB, 0.f);
        float r3 = fmaxf(acc[t][3] - tauB, 0.f);
        acc[t][0] = r0 * r0; pA += acc[t][0];
        acc[t][1] = r1 * r1; pA += acc[t][1];
        acc[t][2] = r2 * r2; pB += acc[t][2];
        acc[t][3] = r3 * r3; pB += acc[t][3];
    }
    pA += __shfl_xor_sync(0xffffffffu, pA, 1);
    pA += __shfl_xor_sync(0xffffffffu, pA, 2);
    pB += __shfl_xor_sync(0xffffffffu, pB, 1);
    pB += __shfl_xor_sync(0xffffffffu, pB, 2);
    const float invA = __fdividef(1.0f, pA);
    const float invB = __fdividef(1.0f, pB);

    // ---- transpose normalized p through smem, then coalesced V*p store ----
    __syncthreads();   // all warps done with X smem (mainloop LDSM complete)
    float* att = (float*)smem;   // [128][ASTRIDE]
    const int rowA = mw + g;
    const int rowB = rowA + 8;
#pragma unroll
    for (int t = 0; t < 16; t++) {
        int col = t * 8 + 2 * tg;
        *(float2*)(att + rowA * ASTRIDE + col) = make_float2(acc[t][0] * invA, acc[t][1] * invA);
        *(float2*)(att + rowB * ASTRIDE + col) = make_float2(acc[t][2] * invB, acc[t][3] * invB);
    }
    __syncthreads();

    // writer: warp w handles row it*8 + w; lane = float4 column (fully coalesced)
    const float4* V4 = (const float4*)Vg + hp * 128 * 32;   // rows hp*128..hp*128+127
    float4* O4 = (float4*)out;
#pragma unroll
    for (int it = 0; it < 16; it++) {
        const int row = it * 8 + wid;          // 0..127  (== k_local*64 + o)
        float4 a = *(const float4*)(att + row * ASTRIDE + lane * 4);
        float4 v = V4[row * 32 + lane];
        const int kk = hp * 2 + (row >> 6), o = row & 63;
        float4 w;
        w.x = a.x * v.x; w.y = a.y * v.y; w.z = a.z * v.z; w.w = a.w * v.w;
        O4[(((size_t)b * KH + kk) * O_ + o) * 32 + lane] = w;
    }
}

// ---------------------------------------------------------------------------
extern "C" void kernel_launch(void* const* d_in, const int* in_sizes, int n_in,
                              void* d_out, int out_size) {
    const float* x = (const float*)d_in[0];   // [2048,128,128]
    const float* w = (const float*)d_in[1];   // [8,128,64]
    const float* q = (const float*)d_in[2];   // [8,64,64]
    const float* v = (const float*)d_in[3];   // [8,64,128]
    float* out = (float*)d_out;               // [2048,8,64,128]

    cudaFuncSetAttribute(main_kernel, cudaFuncAttributeMaxDynamicSharedMemorySize, SM_TOTAL);

    prep_kernel<<<64, 256>>>(w, q);
    main_kernel<<<B_ * 4, 256, SM_TOTAL>>>(x, v, out);
}

// round 6
// speedup vs baseline: 1.8978x; 1.1523x over previous
#include <cuda_runtime.h>
#include <cuda_bf16.h>
#include <cstdint>

#define B_   2048
#define F_   128
#define E_   128
#define KH   8
#define O_   64
#define FOLD 0.0625f     // (alpha-1) * d_k^-0.5 folded into C
#define NIT  8           // Newton iterations

// ---------------- device scratch ----------------
// A in MMA-fragment order: [hp][wid][kt][reg][lane] u32
__device__ __align__(16) uint32_t g_FH[4 * 8 * 8 * 8 * 32];   // 256 KB (hi)
__device__ __align__(16) uint32_t g_FL[4 * 8 * 8 * 8 * 32];   // 256 KB (lo)

// smem: Xh [128][272B] + Xl [128][272B] (persist all passes) + att half [64][132] f32
#define XSTRIDE 272
#define XLOFF   (128 * XSTRIDE)
#define ATT_OFF (2 * 128 * XSTRIDE)          // 69632
#define ASTRIDE 132
#define SM_TOTAL (ATT_OFF + 64 * ASTRIDE * 4)   // 69632 + 33792 = 103424 B

__device__ __forceinline__ uint32_t smem_u32(const void* p) {
    uint32_t a;
    asm("{ .reg .u64 t; cvta.to.shared.u64 t, %1; cvt.u32.u64 %0, t; }" : "=r"(a) : "l"(p));
    return a;
}

__device__ __forceinline__ void mma_bf16(float* d,
                                         uint32_t a0, uint32_t a1, uint32_t a2, uint32_t a3,
                                         uint32_t b0, uint32_t b1) {
    asm volatile("mma.sync.aligned.m16n8k16.row.col.f32.bf16.bf16.f32 "
                 "{%0,%1,%2,%3}, {%4,%5,%6,%7}, {%8,%9}, {%0,%1,%2,%3};"
                 : "+f"(d[0]), "+f"(d[1]), "+f"(d[2]), "+f"(d[3])
                 : "r"(a0), "r"(a1), "r"(a2), "r"(a3), "r"(b0), "r"(b1));
}

__device__ __forceinline__ void ldmx4(uint32_t& b0, uint32_t& b1, uint32_t& b2, uint32_t& b3,
                                      uint32_t addr) {
    asm volatile("ldmatrix.sync.aligned.m8n8.x4.shared.b16 {%0,%1,%2,%3}, [%4];"
                 : "=r"(b0), "=r"(b1), "=r"(b2), "=r"(b3) : "r"(addr));
}

// ---------------------------------------------------------------------------
// prep: C = FOLD * W*Q^T per head, bf16 hi/lo split, stored in fragment order
// ---------------------------------------------------------------------------
#define QS_STRIDE 65
__global__ __launch_bounds__(256)
void prep_kernel(const float* __restrict__ W, const float* __restrict__ Q) {
    __shared__ float qs[64 * QS_STRIDE];   // [o][y], padded
    __shared__ float ws[16 * 64];          // [xl][y]
    const int tid = threadIdx.x;
    const int k   = blockIdx.x >> 3;
    const int x0  = (blockIdx.x & 7) * 16;

    for (int i = tid; i < 4096; i += 256)
        qs[(i >> 6) * QS_STRIDE + (i & 63)] = Q[k * 4096 + i];
    for (int i = tid; i < 1024; i += 256)
        ws[i] = W[(k * 128 + x0) * 64 + i];
    __syncthreads();

    const int hp = k >> 1;
    const int mb = (k & 1) * 64;
#pragma unroll
    for (int j = 0; j < 4; j++) {
        int xo = tid + j * 256;
        int xl = xo >> 6, o = xo & 63;
        const float* wr = ws + xl * 64;
        const float* qr = qs + o * QS_STRIDE;
        float acc = 0.0f;
#pragma unroll
        for (int y = 0; y < 64; y++) acc = fmaf(wr[y], qr[y], acc);
        acc *= FOLD;
        __nv_bfloat16 h = __float2bfloat16(acc);
        __nv_bfloat16 l = __float2bfloat16(acc - __bfloat162float(h));

        const int m   = mb + o;
        const int x   = x0 + xl;
        const int wid = m >> 4, g = m & 7, pA = (m >> 3) & 1;
        const int kt  = x >> 4, xr = x & 15;
        const int hi8 = (xr >> 3) & 1, tg = (xr >> 1) & 3, half = x & 1;
        const int r    = pA + 2 * hi8;
        const int lane = g * 4 + tg;
        const int idx2 = ((((hp * 8 + wid) * 8 + kt) * 8 + r) * 32 + lane) * 2 + half;
        ((__nv_bfloat16*)g_FH)[idx2] = h;
        ((__nv_bfloat16*)g_FL)[idx2] = l;
    }
}

// ---------------------------------------------------------------------------
// main: one CTA per b; stage X once, loop 4 head-pairs:
//       HMMA 3-term GEMM -> entmax-1.5 (Newton) -> *values (transposed store)
// ---------------------------------------------------------------------------
__global__ __launch_bounds__(256, 2)
void main_kernel(const float* __restrict__ Xg, const float* __restrict__ Vg,
                 float* __restrict__ out) {
    extern __shared__ char smem[];
    const int tid  = threadIdx.x;
    const int wid  = tid >> 5;
    const int lane = tid & 31;
    const int b    = blockIdx.x;
    const int mw   = wid * 16;

    // ---- stage X[b]: fp32 -> bf16 hi/lo into smem (once per b) ----
    {
        const float4* Xb4 = (const float4*)(Xg + (size_t)b * F_ * E_);
#pragma unroll
        for (int i = tid; i < 4096; i += 256) {
            int row = i >> 5, c = i & 31;
            float4 v = Xb4[i];
            uint2 hi, lo;
            __nv_bfloat16 h0 = __float2bfloat16(v.x), h1 = __float2bfloat16(v.y);
            __nv_bfloat16 h2 = __float2bfloat16(v.z), h3 = __float2bfloat16(v.w);
            __nv_bfloat162 p01{h0, h1}, p23{h2, h3};
            hi.x = *(uint32_t*)&p01; hi.y = *(uint32_t*)&p23;
            __nv_bfloat162 l01{__float2bfloat16(v.x - __bfloat162float(h0)),
                               __float2bfloat16(v.y - __bfloat162float(h1))};
            __nv_bfloat162 l23{__float2bfloat16(v.z - __bfloat162float(h2)),
                               __float2bfloat16(v.w - __bfloat162float(h3))};
            lo.x = *(uint32_t*)&l01; lo.y = *(uint32_t*)&l23;
            *(uint2*)(smem + row * XSTRIDE + c * 8)         = hi;
            *(uint2*)(smem + XLOFF + row * XSTRIDE + c * 8) = lo;
        }
    }
    __syncthreads();

    const int g  = lane >> 2;
    const int tg = lane & 3;
    const int ln  = (lane & 7) + ((lane >> 4) << 3);
    const int lk8 = (lane >> 3) & 1;
    const uint32_t sbase = smem_u32(smem);
    float* att = (float*)(smem + ATT_OFF);       // [64][ASTRIDE]
    const float4* V4 = (const float4*)Vg;
    float4* O4 = (float4*)out;
    const int rowA = mw + g;        // 0..127
    const int rowB = rowA + 8;

#pragma unroll 1
    for (int hp = 0; hp < 4; hp++) {
        // ---- MMA mainloop ----
        float acc[16][4];
#pragma unroll
        for (int t = 0; t < 16; t++)
#pragma unroll
            for (int j = 0; j < 4; j++) acc[t][j] = 0.0f;

        const uint32_t* FHw = g_FH + (hp * 8 + wid) * (8 * 8 * 32) + lane;
        const uint32_t* FLw = g_FL + (hp * 8 + wid) * (8 * 8 * 32) + lane;

#pragma unroll
        for (int kt = 0; kt < 8; kt++) {
            const uint32_t* FH = FHw + kt * 256;
            const uint32_t* FL = FLw + kt * 256;
            uint32_t a0 = FH[0], a1 = FH[32], a2 = FH[64], a3 = FH[96];
            uint32_t c0 = FL[0], c1 = FL[32], c2 = FL[64], c3 = FL[96];
            uint32_t raddr = sbase + (uint32_t)(ln * XSTRIDE + (kt * 2 + lk8) * 16);
#pragma unroll
            for (int nt2 = 0; nt2 < 8; nt2++) {
                uint32_t roff = raddr + (uint32_t)(nt2 * 16 * XSTRIDE);
                uint32_t b0, b1, b2, b3, l0, l1, l2, l3;
                ldmx4(b0, b1, b2, b3, roff);
                ldmx4(l0, l1, l2, l3, roff + (uint32_t)XLOFF);
                mma_bf16(acc[2 * nt2],     a0, a1, a2, a3, b0, b1);
                mma_bf16(acc[2 * nt2 + 1], a0, a1, a2, a3, b2, b3);
                mma_bf16(acc[2 * nt2],     a0, a1, a2, a3, l0, l1);
                mma_bf16(acc[2 * nt2 + 1], a0, a1, a2, a3, l2, l3);
                mma_bf16(acc[2 * nt2],     c0, c1, c2, c3, b0, b1);
                mma_bf16(acc[2 * nt2 + 1], c0, c1, c2, c3, b2, b3);
            }
        }

        // ---- entmax-1.5, fully warp-local ----
        float mA = acc[0][0], mB = acc[0][2];
#pragma unroll
        for (int t = 0; t < 16; t++) {
            mA = fmaxf(mA, fmaxf(acc[t][0], acc[t][1]));
            mB = fmaxf(mB, fmaxf(acc[t][2], acc[t][3]));
        }
        mA = fmaxf(mA, __shfl_xor_sync(0xffffffffu, mA, 1));
        mA = fmaxf(mA, __shfl_xor_sync(0xffffffffu, mA, 2));
        mB = fmaxf(mB, __shfl_xor_sync(0xffffffffu, mB, 1));
        mB = fmaxf(mB, __shfl_xor_sync(0xffffffffu, mB, 2));

        float tauA = mA - 1.0f, tauB = mB - 1.0f;

#pragma unroll 1
        for (int it = 0; it < NIT; it++) {
            float sA = 0.f, qA = 0.f, sB = 0.f, qB = 0.f;
#pragma unroll
            for (int t = 0; t < 16; t++) {
                float r0 = fmaxf(acc[t][0] - tauA, 0.f);
                float r1 = fmaxf(acc[t][1] - tauA, 0.f);
                float r2 = fmaxf(acc[t][2] - tauB, 0.f);
                float r3 = fmaxf(acc[t][3] - tauB, 0.f);
                qA = fmaf(r0, r0, qA); sA += r0;
                qA = fmaf(r1, r1, qA); sA += r1;
                qB = fmaf(r2, r2, qB); sB += r2;
                qB = fmaf(r3, r3, qB); sB += r3;
            }
            qA += __shfl_xor_sync(0xffffffffu, qA, 1);
            qA += __shfl_xor_sync(0xffffffffu, qA, 2);
            sA += __shfl_xor_sync(0xffffffffu, sA, 1);
            sA += __shfl_xor_sync(0xffffffffu, sA, 2);
            qB += __shfl_xor_sync(0xffffffffu, qB, 1);
            qB += __shfl_xor_sync(0xffffffffu, qB, 2);
            sB += __shfl_xor_sync(0xffffffffu, sB, 1);
            sB += __shfl_xor_sync(0xffffffffu, sB, 2);
            tauA += __fdividef(qA - 1.0f, 2.0f * sA);
            tauB += __fdividef(qB - 1.0f, 2.0f * sB);
        }

        float pA = 0.f, pB = 0.f;
#pragma unroll
        for (int t = 0; t < 16; t++) {
            float r0 = fmaxf(acc[t][0] - tauA, 0.f);
            float r1 = fmaxf(acc[t][1] - tauA, 0.f);
            float r2 = fmaxf(acc[t][2] - tauB, 0.f);
            float r3 = fmaxf(acc[t][3] - tauB, 0.f);
            acc[t][0] = r0 * r0; pA += acc[t][0];
            acc[t][1] = r1 * r1; pA += acc[t][1];
            acc[t][2] = r2 * r2; pB += acc[t][2];
            acc[t][3] = r3 * r3; pB += acc[t][3];
        }
        pA += __shfl_xor_sync(0xffffffffu, pA, 1);
        pA += __shfl_xor_sync(0xffffffffu, pA, 2);
        pB += __shfl_xor_sync(0xffffffffu, pB, 1);
        pB += __shfl_xor_sync(0xffffffffu, pB, 2);
        const float invA = __fdividef(1.0f, pA);
        const float invB = __fdividef(1.0f, pB);

        // ---- half 0: rows 0..63 (head 2hp), owned by warps 0-3 ----
        if (wid < 4) {
#pragma unroll
            for (int t = 0; t < 16; t++) {
                int col = t * 8 + 2 * tg;
                *(float2*)(att + rowA * ASTRIDE + col) = make_float2(acc[t][0] * invA, acc[t][1] * invA);
                *(float2*)(att + rowB * ASTRIDE + col) = make_float2(acc[t][2] * invB, acc[t][3] * invB);
            }
        }
        __syncthreads();
#pragma unroll
        for (int it = 0; it < 8; it++) {
            const int r = it * 8 + wid;          // 0..63
            float4 a = *(const float4*)(att + r * ASTRIDE + lane * 4);
            float4 v = V4[(hp * 128 + r) * 32 + lane];
            float4 w;
            w.x = a.x * v.x; w.y = a.y * v.y; w.z = a.z * v.z; w.w = a.w * v.w;
            O4[(((size_t)b * KH + hp * 2) * O_ + r) * 32 + lane] = w;
        }
        __syncthreads();

        // ---- half 1: rows 64..127 (head 2hp+1), owned by warps 4-7 ----
        if (wid >= 4) {
#pragma unroll
            for (int t = 0; t < 16; t++) {
                int col = t * 8 + 2 * tg;
                *(float2*)(att + (rowA - 64) * ASTRIDE + col) = make_float2(acc[t][0] * invA, acc[t][1] * invA);
                *(float2*)(att + (rowB - 64) * ASTRIDE + col) = make_float2(acc[t][2] * invB, acc[t][3] * invB);
            }
        }
        __syncthreads();
#pragma unroll
        for (int it = 0; it < 8; it++) {
            const int r = it * 8 + wid;          // 0..63
            float4 a = *(const float4*)(att + r * ASTRIDE + lane * 4);
            float4 v = V4[(hp * 128 + 64 + r) * 32 + lane];
            float4 w;
            w.x = a.x * v.x; w.y = a.y * v.y; w.z = a.z * v.z; w.w = a.w * v.w;
            O4[(((size_t)b * KH + hp * 2 + 1) * O_ + r) * 32 + lane] = w;
        }
        __syncthreads();
    }
}

// ---------------------------------------------------------------------------
extern "C" void kernel_launch(void* const* d_in, const int* in_sizes, int n_in,
                              void* d_out, int out_size) {
    const float* x = (const float*)d_in[0];   // [2048,128,128]
    const float* w = (const float*)d_in[1];   // [8,128,64]
    const float* q = (const float*)d_in[2];   // [8,64,64]
    const float* v = (const float*)d_in[3];   // [8,64,128]
    float* out = (float*)d_out;               // [2048,8,64,128]

    cudaFuncSetAttribute(main_kernel, cudaFuncAttributeMaxDynamicSharedMemorySize, SM_TOTAL);

    prep_kernel<<<64, 256>>>(w, q);
    main_kernel<<<B_, 256, SM_TOTAL>>>(x, v, out);
}

// round 8
// speedup vs baseline: 2.0645x; 1.0878x over previous
#include <cuda_runtime.h>
#include <cuda_bf16.h>
#include <cstdint>

#define B_   2048
#define F_   128
#define E_   128
#define KH   8
#define O_   64
#define FOLD 0.0625f     // (alpha-1) * d_k^-0.5 folded into C
#define NIT  6           // Newton iterations (packed)

// ---------------- device scratch ----------------
// A in MMA-fragment order: [hp][wid][kt][lane][reg0..3] u32  (one uint4 per lane per kt)
__device__ __align__(16) uint32_t g_FH[4 * 8 * 8 * 32 * 4];   // 128 KB (hi)
__device__ __align__(16) uint32_t g_FL[4 * 8 * 8 * 32 * 4];   // 128 KB (lo)

// smem: Xh [128][272B] + Xl [128][272B] (persist all passes) + att half [64][132] f32
#define XSTRIDE 272
#define XLOFF   (128 * XSTRIDE)
#define ATT_OFF (2 * 128 * XSTRIDE)          // 69632
#define ASTRIDE 132
#define SM_TOTAL (ATT_OFF + 64 * ASTRIDE * 4)   // 103424 B

__device__ __forceinline__ uint32_t smem_u32(const void* p) {
    uint32_t a;
    asm("{ .reg .u64 t; cvta.to.shared.u64 t, %1; cvt.u32.u64 %0, t; }" : "=r"(a) : "l"(p));
    return a;
}

__device__ __forceinline__ void mma_bf16(float* d,
                                         uint32_t a0, uint32_t a1, uint32_t a2, uint32_t a3,
                                         uint32_t b0, uint32_t b1) {
    asm volatile("mma.sync.aligned.m16n8k16.row.col.f32.bf16.bf16.f32 "
                 "{%0,%1,%2,%3}, {%4,%5,%6,%7}, {%8,%9}, {%0,%1,%2,%3};"
                 : "+f"(d[0]), "+f"(d[1]), "+f"(d[2]), "+f"(d[3])
                 : "r"(a0), "r"(a1), "r"(a2), "r"(a3), "r"(b0), "r"(b1));
}

__device__ __forceinline__ void ldmx4(uint32_t& b0, uint32_t& b1, uint32_t& b2, uint32_t& b3,
                                      uint32_t addr) {
    asm volatile("ldmatrix.sync.aligned.m8n8.x4.shared.b16 {%0,%1,%2,%3}, [%4];"
                 : "=r"(b0), "=r"(b1), "=r"(b2), "=r"(b3) : "r"(addr));
}

// packed f32x2 helpers (base Blackwell ISA)
#define ADD2(d, a, b)  asm("add.rn.f32x2 %0, %1, %2;" : "=l"(d) : "l"(a), "l"(b))
#define MUL2(d, a, b)  asm("mul.rn.f32x2 %0, %1, %2;" : "=l"(d) : "l"(a), "l"(b))
#define FMA2ACC(d, a, b) asm("fma.rn.f32x2 %0, %1, %2, %0;" : "+l"(d) : "l"(a), "l"(b))
#define PACK2(d, lo, hi) asm("mov.b64 %0, {%1, %2};" : "=l"(d) : "f"(lo), "f"(hi))
#define UNPK2(lo, hi, s) asm("mov.b64 {%0, %1}, %2;" : "=f"(lo), "=f"(hi) : "l"(s))
#define ABSM 0x7fffffff7fffffffULL

// ---------------------------------------------------------------------------
// prep: C = FOLD * W*Q^T per head, bf16 hi/lo split, stored in fragment order
// ---------------------------------------------------------------------------
#define QS_STRIDE 65
__global__ __launch_bounds__(256)
void prep_kernel(const float* __restrict__ W, const float* __restrict__ Q) {
    __shared__ float qs[64 * QS_STRIDE];   // [o][y], padded
    __shared__ float ws[16 * 64];          // [xl][y]
    const int tid = threadIdx.x;
    const int k   = blockIdx.x >> 3;
    const int x0  = (blockIdx.x & 7) * 16;

    for (int i = tid; i < 4096; i += 256)
        qs[(i >> 6) * QS_STRIDE + (i & 63)] = Q[k * 4096 + i];
    for (int i = tid; i < 1024; i += 256)
        ws[i] = W[(k * 128 + x0) * 64 + i];
    __syncthreads();

    const int hp = k >> 1;
    const int mb = (k & 1) * 64;
#pragma unroll
    for (int j = 0; j < 4; j++) {
        int xo = tid + j * 256;
        int xl = xo >> 6, o = xo & 63;
        const float* wr = ws + xl * 64;
        const float* qr = qs + o * QS_STRIDE;
        float acc = 0.0f;
#pragma unroll
        for (int y = 0; y < 64; y++) acc = fmaf(wr[y], qr[y], acc);
        acc *= FOLD;
        __nv_bfloat16 h = __float2bfloat16(acc);
        __nv_bfloat16 l = __float2bfloat16(acc - __bfloat162float(h));

        const int m   = mb + o;
        const int x   = x0 + xl;
        const int wid = m >> 4, g = m & 7, pA = (m >> 3) & 1;
        const int kt  = x >> 4, xr = x & 15;
        const int hi8 = (xr >> 3) & 1, tg = (xr >> 1) & 3, half = x & 1;
        const int r    = pA + 2 * hi8;
        const int lane = g * 4 + tg;
        const int idx2 = ((((hp * 8 + wid) * 8 + kt) * 32 + lane) * 4 + r) * 2 + half;
        ((__nv_bfloat16*)g_FH)[idx2] = h;
        ((__nv_bfloat16*)g_FL)[idx2] = l;
    }
}

// ---------------------------------------------------------------------------
// main: one CTA per b; stage X once, loop 4 head-pairs:
//       HMMA 3-term GEMM -> entmax-1.5 (packed Newton) -> *values
// ---------------------------------------------------------------------------
__global__ __launch_bounds__(256, 2)
void main_kernel(const float* __restrict__ Xg, const float* __restrict__ Vg,
                 float* __restrict__ out) {
    extern __shared__ char smem[];
    const int tid  = threadIdx.x;
    const int wid  = tid >> 5;
    const int lane = tid & 31;
    const int b    = blockIdx.x;
    const int mw   = wid * 16;

    // ---- stage X[b]: fp32 -> bf16 hi/lo into smem (once per b) ----
    {
        const float4* Xb4 = (const float4*)(Xg + (size_t)b * F_ * E_);
#pragma unroll
        for (int i = tid; i < 4096; i += 256) {
            int row = i >> 5, c = i & 31;
            float4 v = Xb4[i];
            uint2 hi, lo;
            __nv_bfloat16 h0 = __float2bfloat16(v.x), h1 = __float2bfloat16(v.y);
            __nv_bfloat16 h2 = __float2bfloat16(v.z), h3 = __float2bfloat16(v.w);
            __nv_bfloat162 p01{h0, h1}, p23{h2, h3};
            hi.x = *(uint32_t*)&p01; hi.y = *(uint32_t*)&p23;
            __nv_bfloat162 l01{__float2bfloat16(v.x - __bfloat162float(h0)),
                               __float2bfloat16(v.y - __bfloat162float(h1))};
            __nv_bfloat162 l23{__float2bfloat16(v.z - __bfloat162float(h2)),
                               __float2bfloat16(v.w - __bfloat162float(h3))};
            lo.x = *(uint32_t*)&l01; lo.y = *(uint32_t*)&l23;
            *(uint2*)(smem + row * XSTRIDE + c * 8)         = hi;
            *(uint2*)(smem + XLOFF + row * XSTRIDE + c * 8) = lo;
        }
    }
    __syncthreads();

    const int g  = lane >> 2;
    const int tg = lane & 3;
    const int ln  = (lane & 7) + ((lane >> 4) << 3);
    const int lk8 = (lane >> 3) & 1;
    const uint32_t sbase = smem_u32(smem);
    float* att = (float*)(smem + ATT_OFF);       // [64][ASTRIDE]
    const float4* V4 = (const float4*)Vg;
    float4* O4 = (float4*)out;
    const int rowA = mw + g;        // 0..127
    const int rowB = rowA + 8;

#pragma unroll 1
    for (int hp = 0; hp < 4; hp++) {
        // ---- MMA mainloop ----
        float acc[16][4];
#pragma unroll
        for (int t = 0; t < 16; t++)
#pragma unroll
            for (int j = 0; j < 4; j++) acc[t][j] = 0.0f;

        const uint4* FH4 = ((const uint4*)g_FH) + ((hp * 8 + wid) * 8) * 32 + lane;
        const uint4* FL4 = ((const uint4*)g_FL) + ((hp * 8 + wid) * 8) * 32 + lane;

#pragma unroll
        for (int kt = 0; kt < 8; kt++) {
            uint4 ah = FH4[kt * 32];
            uint4 al = FL4[kt * 32];
            uint32_t raddr = sbase + (uint32_t)(ln * XSTRIDE + (kt * 2 + lk8) * 16);
#pragma unroll
            for (int nt2 = 0; nt2 < 8; nt2++) {
                uint32_t roff = raddr + (uint32_t)(nt2 * 16 * XSTRIDE);
                uint32_t b0, b1, b2, b3, l0, l1, l2, l3;
                ldmx4(b0, b1, b2, b3, roff);
                ldmx4(l0, l1, l2, l3, roff + (uint32_t)XLOFF);
                mma_bf16(acc[2 * nt2],     ah.x, ah.y, ah.z, ah.w, b0, b1);
                mma_bf16(acc[2 * nt2 + 1], ah.x, ah.y, ah.z, ah.w, b2, b3);
                mma_bf16(acc[2 * nt2],     ah.x, ah.y, ah.z, ah.w, l0, l1);
                mma_bf16(acc[2 * nt2 + 1], ah.x, ah.y, ah.z, ah.w, l2, l3);
                mma_bf16(acc[2 * nt2],     al.x, al.y, al.z, al.w, b0, b1);
                mma_bf16(acc[2 * nt2 + 1], al.x, al.y, al.z, al.w, b2, b3);
            }
        }

        // ---- row max (warp-local) ----
        float mA = acc[0][0], mB = acc[0][2];
#pragma unroll
        for (int t = 0; t < 16; t++) {
            mA = fmaxf(mA, fmaxf(acc[t][0], acc[t][1]));
            mB = fmaxf(mB, fmaxf(acc[t][2], acc[t][3]));
        }
        mA = fmaxf(mA, __shfl_xor_sync(0xffffffffu, mA, 1));
        mA = fmaxf(mA, __shfl_xor_sync(0xffffffffu, mA, 2));
        mB = fmaxf(mB, __shfl_xor_sync(0xffffffffu, mB, 1));
        mB = fmaxf(mB, __shfl_xor_sync(0xffffffffu, mB, 2));

        // ---- pack z into f32x2 (replaces acc registers) ----
        unsigned long long zA[16], zB[16];
#pragma unroll
        for (int t = 0; t < 16; t++) {
            PACK2(zA[t], acc[t][0], acc[t][1]);
            PACK2(zB[t], acc[t][2], acc[t][3]);
        }

        float tauA = mA - 1.0f, tauB = mB - 1.0f;

        // ---- packed Newton: r' = t + |t| = 2*max(t,0); tau += (Q-4)/(4S) ----
#pragma unroll 1
        for (int it = 0; it < NIT; it++) {
            unsigned long long nA2, nB2;
            unsigned long long qA2 = 0ULL, sA2 = 0ULL, qB2 = 0ULL, sB2 = 0ULL;
            float ntA = -tauA, ntB = -tauB;
            PACK2(nA2, ntA, ntA);
            PACK2(nB2, ntB, ntB);
#pragma unroll
            for (int t = 0; t < 16; t++) {
                unsigned long long t2, r2;
                ADD2(t2, zA[t], nA2);
                r2 = t2 & ABSM;
                ADD2(r2, t2, r2);
                FMA2ACC(qA2, r2, r2);
                ADD2(sA2, sA2, r2);
                ADD2(t2, zB[t], nB2);
                r2 = t2 & ABSM;
                ADD2(r2, t2, r2);
                FMA2ACC(qB2, r2, r2);
                ADD2(sB2, sB2, r2);
            }
            float q0, q1, s0, s1;
            UNPK2(q0, q1, qA2); UNPK2(s0, s1, sA2);
            float qA = q0 + q1, sA = s0 + s1;
            UNPK2(q0, q1, qB2); UNPK2(s0, s1, sB2);
            float qB = q0 + q1, sB = s0 + s1;
            qA += __shfl_xor_sync(0xffffffffu, qA, 1);
            qA += __shfl_xor_sync(0xffffffffu, qA, 2);
            sA += __shfl_xor_sync(0xffffffffu, sA, 1);
            sA += __shfl_xor_sync(0xffffffffu, sA, 2);
            qB += __shfl_xor_sync(0xffffffffu, qB, 1);
            qB += __shfl_xor_sync(0xffffffffu, qB, 2);
            sB += __shfl_xor_sync(0xffffffffu, sB, 1);
            sB += __shfl_xor_sync(0xffffffffu, sB, 2);
            tauA += __fdividef(qA - 4.0f, 4.0f * sA);
            tauB += __fdividef(qB - 4.0f, 4.0f * sB);
        }

        // ---- final p = r'^2 (scale cancels in normalization), psum, inv ----
        {
            unsigned long long nA2, nB2, pA2 = 0ULL, pB2 = 0ULL;
            float ntA = -tauA, ntB = -tauB;
            PACK2(nA2, ntA, ntA);
            PACK2(nB2, ntB, ntB);
#pragma unroll
            for (int t = 0; t < 16; t++) {
                unsigned long long t2, r2, p2;
                ADD2(t2, zA[t], nA2);
                r2 = t2 & ABSM;
                ADD2(r2, t2, r2);
                MUL2(p2, r2, r2);
                zA[t] = p2;
                ADD2(pA2, pA2, p2);
                ADD2(t2, zB[t], nB2);
                r2 = t2 & ABSM;
                ADD2(r2, t2, r2);
                MUL2(p2, r2, r2);
                zB[t] = p2;
                ADD2(pB2, pB2, p2);
            }
            float p0, p1;
            UNPK2(p0, p1, pA2); float psA = p0 + p1;
            UNPK2(p0, p1, pB2); float psB = p0 + p1;
            psA += __shfl_xor_sync(0xffffffffu, psA, 1);
            psA += __shfl_xor_sync(0xffffffffu, psA, 2);
            psB += __shfl_xor_sync(0xffffffffu, psB, 1);
            psB += __shfl_xor_sync(0xffffffffu, psB, 2);
            const float invA = __fdividef(1.0f, psA);
            const float invB = __fdividef(1.0f, psB);

            // ---- half 0: rows 0..63 (head 2hp), warps 0-3 ----
            __syncthreads();
            if (wid < 4) {
#pragma unroll
                for (int t = 0; t < 16; t++) {
                    int col = t * 8 + 2 * tg;
                    float f0, f1;
                    UNPK2(f0, f1, zA[t]);
                    *(float2*)(att + rowA * ASTRIDE + col) = make_float2(f0 * invA, f1 * invA);
                    UNPK2(f0, f1, zB[t]);
                    *(float2*)(att + rowB * ASTRIDE + col) = make_float2(f0 * invB, f1 * invB);
                }
            }
            __syncthreads();
#pragma unroll
            for (int it = 0; it < 8; it++) {
                const int r = it * 8 + wid;
                float4 a = *(const float4*)(att + r * ASTRIDE + lane * 4);
                float4 v = V4[(hp * 128 + r) * 32 + lane];
                float4 w;
                w.x = a.x * v.x; w.y = a.y * v.y; w.z = a.z * v.z; w.w = a.w * v.w;
                O4[(((size_t)b * KH + hp * 2) * O_ + r) * 32 + lane] = w;
            }
            __syncthreads();

            // ---- half 1: rows 64..127 (head 2hp+1), warps 4-7 ----
            if (wid >= 4) {
#pragma unroll
                for (int t = 0; t < 16; t++) {
                    int col = t * 8 + 2 * tg;
                    float f0, f1;
                    UNPK2(f0, f1, zA[t]);
                    *(float2*)(att + (rowA - 64) * ASTRIDE + col) = make_float2(f0 * invA, f1 * invA);
                    UNPK2(f0, f1, zB[t]);
                    *(float2*)(att + (rowB - 64) * ASTRIDE + col) = make_float2(f0 * invB, f1 * invB);
                }
            }
            __syncthreads();
#pragma unroll
            for (int it = 0; it < 8; it++) {
                const int r = it * 8 + wid;
                float4 a = *(const float4*)(att + r * ASTRIDE + lane * 4);
                float4 v = V4[(hp * 128 + 64 + r) * 32 + lane];
                float4 w;
                w.x = a.x * v.x; w.y = a.y * v.y; w.z = a.z * v.z; w.w = a.w * v.w;
                O4[(((size_t)b * KH + hp * 2 + 1) * O_ + r) * 32 + lane] = w;
            }
            __syncthreads();
        }
    }
}

// ---------------------------------------------------------------------------
extern "C" void kernel_launch(void* const* d_in, const int* in_sizes, int n_in,
                              void* d_out, int out_size) {
    const float* x = (const float*)d_in[0];   // [2048,128,128]
    const float* w = (const float*)d_in[1];   // [8,128,64]
    const float* q = (const float*)d_in[2];   // [8,64,64]
    const float* v = (const float*)d_in[3];   // [8,64,128]
    float* out = (float*)d_out;               // [2048,8,64,128]

    cudaFuncSetAttribute(main_kernel, cudaFuncAttributeMaxDynamicSharedMemorySize, SM_TOTAL);

    prep_kernel<<<64, 256>>>(w, q);
    main_kernel<<<B_, 256, SM_TOTAL>>>(x, v, out);
}

// round 10
// speedup vs baseline: 2.0690x; 1.0022x over previous
#include <cuda_runtime.h>
#include <cuda_bf16.h>
#include <cstdint>

#define B_   2048
#define F_   128
#define E_   128
#define KH   8
#define O_   64
#define FOLD 0.0625f     // (alpha-1) * d_k^-0.5 folded into C
#define NIT  6           // Newton iterations (packed) — 5 is NOT enough (R9: 3.1e-3)

// ---------------- device scratch ----------------
// A in MMA-fragment order: [hp][wid][kt][lane][reg0..3] u32  (one uint4 per lane per kt)
__device__ __align__(16) uint32_t g_FH[4 * 8 * 8 * 32 * 4];   // 128 KB (hi)
__device__ __align__(16) uint32_t g_FL[4 * 8 * 8 * 32 * 4];   // 128 KB (lo)

// smem: Xh [128][272B] + Xl [128][272B] (persist all passes) + att half [64][132] f32
#define XSTRIDE 272
#define XLOFF   (128 * XSTRIDE)
#define ATT_OFF (2 * 128 * XSTRIDE)          // 69632
#define ASTRIDE 132
#define SM_TOTAL (ATT_OFF + 64 * ASTRIDE * 4)   // 103424 B

__device__ __forceinline__ uint32_t smem_u32(const void* p) {
    uint32_t a;
    asm("{ .reg .u64 t; cvta.to.shared.u64 t, %1; cvt.u32.u64 %0, t; }" : "=r"(a) : "l"(p));
    return a;
}

__device__ __forceinline__ void mma_bf16(float* d, const uint4& a,
                                         uint32_t b0, uint32_t b1) {
    asm volatile("mma.sync.aligned.m16n8k16.row.col.f32.bf16.bf16.f32 "
                 "{%0,%1,%2,%3}, {%4,%5,%6,%7}, {%8,%9}, {%0,%1,%2,%3};"
                 : "+f"(d[0]), "+f"(d[1]), "+f"(d[2]), "+f"(d[3])
                 : "r"(a.x), "r"(a.y), "r"(a.z), "r"(a.w), "r"(b0), "r"(b1));
}

__device__ __forceinline__ void ldmx4(uint32_t& b0, uint32_t& b1, uint32_t& b2, uint32_t& b3,
                                      uint32_t addr) {
    asm volatile("ldmatrix.sync.aligned.m8n8.x4.shared.b16 {%0,%1,%2,%3}, [%4];"
                 : "=r"(b0), "=r"(b1), "=r"(b2), "=r"(b3) : "r"(addr));
}

// packed f32x2 helpers (base Blackwell ISA)
#define ADD2(d, a, b)  asm("add.rn.f32x2 %0, %1, %2;" : "=l"(d) : "l"(a), "l"(b))
#define MUL2(d, a, b)  asm("mul.rn.f32x2 %0, %1, %2;" : "=l"(d) : "l"(a), "l"(b))
#define FMA2ACC(d, a, b) asm("fma.rn.f32x2 %0, %1, %2, %0;" : "+l"(d) : "l"(a), "l"(b))
#define PACK2(d, lo, hi) asm("mov.b64 %0, {%1, %2};" : "=l"(d) : "f"(lo), "f"(hi))
#define UNPK2(lo, hi, s) asm("mov.b64 {%0, %1}, %2;" : "=f"(lo), "=f"(hi) : "l"(s))
#define ABSM 0x7fffffff7fffffffULL

// ---------------------------------------------------------------------------
// prep: C = FOLD * W*Q^T per head, bf16 hi/lo split, stored in fragment order
// ---------------------------------------------------------------------------
#define QS_STRIDE 65
__global__ __launch_bounds__(256)
void prep_kernel(const float* __restrict__ W, const float* __restrict__ Q) {
    __shared__ float qs[64 * QS_STRIDE];   // [o][y], padded
    __shared__ float ws[16 * 64];          // [xl][y]
    const int tid = threadIdx.x;
    const int k   = blockIdx.x >> 3;
    const int x0  = (blockIdx.x & 7) * 16;

    for (int i = tid; i < 4096; i += 256)
        qs[(i >> 6) * QS_STRIDE + (i & 63)] = Q[k * 4096 + i];
    for (int i = tid; i < 1024; i += 256)
        ws[i] = W[(k * 128 + x0) * 64 + i];
    __syncthreads();

    const int hp = k >> 1;
    const int mb = (k & 1) * 64;
#pragma unroll
    for (int j = 0; j < 4; j++) {
        int xo = tid + j * 256;
        int xl = xo >> 6, o = xo & 63;
        const float* wr = ws + xl * 64;
        const float* qr = qs + o * QS_STRIDE;
        float acc = 0.0f;
#pragma unroll
        for (int y = 0; y < 64; y++) acc = fmaf(wr[y], qr[y], acc);
        acc *= FOLD;
        __nv_bfloat16 h = __float2bfloat16(acc);
        __nv_bfloat16 l = __float2bfloat16(acc - __bfloat162float(h));

        const int m   = mb + o;
        const int x   = x0 + xl;
        const int wid = m >> 4, g = m & 7, pA = (m >> 3) & 1;
        const int kt  = x >> 4, xr = x & 15;
        const int hi8 = (xr >> 3) & 1, tg = (xr >> 1) & 3, half = x & 1;
        const int r    = pA + 2 * hi8;
        const int lane = g * 4 + tg;
        const int idx2 = ((((hp * 8 + wid) * 8 + kt) * 32 + lane) * 4 + r) * 2 + half;
        ((__nv_bfloat16*)g_FH)[idx2] = h;
        ((__nv_bfloat16*)g_FL)[idx2] = l;
    }
}

// ---------------------------------------------------------------------------
// main: one CTA per b; stage X once, loop 4 head-pairs:
//       HMMA 3-term GEMM (pipelined) -> entmax-1.5 (packed Newton) -> *values
// ---------------------------------------------------------------------------
__global__ __launch_bounds__(256, 2)
void main_kernel(const float* __restrict__ Xg, const float* __restrict__ Vg,
                 float* __restrict__ out) {
    extern __shared__ char smem[];
    const int tid  = threadIdx.x;
    const int wid  = tid >> 5;
    const int lane = tid & 31;
    const int b    = blockIdx.x;
    const int mw   = wid * 16;

    // ---- stage X[b]: fp32 -> bf16 hi/lo into smem (once per b) ----
    {
        const float4* Xb4 = (const float4*)(Xg + (size_t)b * F_ * E_);
#pragma unroll
        for (int i = tid; i < 4096; i += 256) {
            int row = i >> 5, c = i & 31;
            float4 v = Xb4[i];
            uint2 hi, lo;
            __nv_bfloat16 h0 = __float2bfloat16(v.x), h1 = __float2bfloat16(v.y);
            __nv_bfloat16 h2 = __float2bfloat16(v.z), h3 = __float2bfloat16(v.w);
            __nv_bfloat162 p01{h0, h1}, p23{h2, h3};
            hi.x = *(uint32_t*)&p01; hi.y = *(uint32_t*)&p23;
            __nv_bfloat162 l01{__float2bfloat16(v.x - __bfloat162float(h0)),
                               __float2bfloat16(v.y - __bfloat162float(h1))};
            __nv_bfloat162 l23{__float2bfloat16(v.z - __bfloat162float(h2)),
                               __float2bfloat16(v.w - __bfloat162float(h3))};
            lo.x = *(uint32_t*)&l01; lo.y = *(uint32_t*)&l23;
            *(uint2*)(smem + row * XSTRIDE + c * 8)         = hi;
            *(uint2*)(smem + XLOFF + row * XSTRIDE + c * 8) = lo;
        }
    }
    __syncthreads();

    const int g  = lane >> 2;
    const int tg = lane & 3;
    const int ln  = (lane & 7) + ((lane >> 4) << 3);
    const int lk8 = (lane >> 3) & 1;
    const uint32_t sbase = smem_u32(smem);
    float* att = (float*)(smem + ATT_OFF);       // [64][ASTRIDE]
    const float4* V4 = (const float4*)Vg;
    float4* O4 = (float4*)out;
    const int rowA = mw + g;        // 0..127
    const int rowB = rowA + 8;

#pragma unroll 1
    for (int hp = 0; hp < 4; hp++) {
        // ---- MMA mainloop (A-prefetch + nt2-pair batching, acc distance 4) ----
        float acc[16][4];
#pragma unroll
        for (int t = 0; t < 16; t++)
#pragma unroll
            for (int j = 0; j < 4; j++) acc[t][j] = 0.0f;

        const uint4* FH4 = ((const uint4*)g_FH) + ((hp * 8 + wid) * 8) * 32 + lane;
        const uint4* FL4 = ((const uint4*)g_FL) + ((hp * 8 + wid) * 8) * 32 + lane;

        uint4 ah = FH4[0];
        uint4 al = FL4[0];
#pragma unroll
        for (int kt = 0; kt < 8; kt++) {
            const int ktn = (kt < 7) ? kt + 1 : 7;
            uint4 ahn = FH4[ktn * 32];
            uint4 aln = FL4[ktn * 32];
            uint32_t raddr = sbase + (uint32_t)(ln * XSTRIDE + (kt * 2 + lk8) * 16);
#pragma unroll
            for (int j = 0; j < 4; j++) {
                uint32_t r0a = raddr + (uint32_t)((2 * j) * 16 * XSTRIDE);
                uint32_t r1a = raddr + (uint32_t)((2 * j + 1) * 16 * XSTRIDE);
                uint32_t b0, b1, b2, b3, c0, c1, c2, c3;
                uint32_t lb0, lb1, lb2, lb3, lc0, lc1, lc2, lc3;
                ldmx4(b0, b1, b2, b3, r0a);
                ldmx4(lb0, lb1, lb2, lb3, r0a + (uint32_t)XLOFF);
                ldmx4(c0, c1, c2, c3, r1a);
                ldmx4(lc0, lc1, lc2, lc3, r1a + (uint32_t)XLOFF);
                float* A0 = acc[4 * j];
                float* A1 = acc[4 * j + 1];
                float* A2 = acc[4 * j + 2];
                float* A3 = acc[4 * j + 3];
                mma_bf16(A0, ah, b0, b1);
                mma_bf16(A1, ah, b2, b3);
                mma_bf16(A2, ah, c0, c1);
                mma_bf16(A3, ah, c2, c3);
                mma_bf16(A0, ah, lb0, lb1);
                mma_bf16(A1, ah, lb2, lb3);
                mma_bf16(A2, ah, lc0, lc1);
                mma_bf16(A3, ah, lc2, lc3);
                mma_bf16(A0, al, b0, b1);
                mma_bf16(A1, al, b2, b3);
                mma_bf16(A2, al, c0, c1);
                mma_bf16(A3, al, c2, c3);
            }
            ah = ahn;
            al = aln;
        }

        // ---- row max (warp-local) ----
        float mA = acc[0][0], mB = acc[0][2];
#pragma unroll
        for (int t = 0; t < 16; t++) {
            mA = fmaxf(mA, fmaxf(acc[t][0], acc[t][1]));
            mB = fmaxf(mB, fmaxf(acc[t][2], acc[t][3]));
        }
        mA = fmaxf(mA, __shfl_xor_sync(0xffffffffu, mA, 1));
        mA = fmaxf(mA, __shfl_xor_sync(0xffffffffu, mA, 2));
        mB = fmaxf(mB, __shfl_xor_sync(0xffffffffu, mB, 1));
        mB = fmaxf(mB, __shfl_xor_sync(0xffffffffu, mB, 2));

        // ---- pack z into f32x2 (replaces acc registers) ----
        unsigned long long zA[16], zB[16];
#pragma unroll
        for (int t = 0; t < 16; t++) {
            PACK2(zA[t], acc[t][0], acc[t][1]);
            PACK2(zB[t], acc[t][2], acc[t][3]);
        }

        float tauA = mA - 1.0f, tauB = mB - 1.0f;

        // ---- packed Newton, 2-way split chains: r' = t+|t|; tau += (Q-4)/(4S) ----
#pragma unroll 1
        for (int it = 0; it < NIT; it++) {
            unsigned long long nA2, nB2;
            unsigned long long qAa = 0, qAb = 0, sAa = 0, sAb = 0;
            unsigned long long qBa = 0, qBb = 0, sBa = 0, sBb = 0;
            float ntA = -tauA, ntB = -tauB;
            PACK2(nA2, ntA, ntA);
            PACK2(nB2, ntB, ntB);
#pragma unroll
            for (int t = 0; t < 16; t += 2) {
                unsigned long long t2, r2;
                ADD2(t2, zA[t], nA2);
                r2 = t2 & ABSM;
                ADD2(r2, t2, r2);
                FMA2ACC(qAa, r2, r2);
                ADD2(sAa, sAa, r2);
                ADD2(t2, zA[t + 1], nA2);
                r2 = t2 & ABSM;
                ADD2(r2, t2, r2);
                FMA2ACC(qAb, r2, r2);
                ADD2(sAb, sAb, r2);
                ADD2(t2, zB[t], nB2);
                r2 = t2 & ABSM;
                ADD2(r2, t2, r2);
                FMA2ACC(qBa, r2, r2);
                ADD2(sBa, sBa, r2);
                ADD2(t2, zB[t + 1], nB2);
                r2 = t2 & ABSM;
                ADD2(r2, t2, r2);
                FMA2ACC(qBb, r2, r2);
                ADD2(sBb, sBb, r2);
            }
            unsigned long long qA2, sA2, qB2, sB2;
            ADD2(qA2, qAa, qAb);
            ADD2(sA2, sAa, sAb);
            ADD2(qB2, qBa, qBb);
            ADD2(sB2, sBa, sBb);
            float q0, q1, s0, s1;
            UNPK2(q0, q1, qA2); UNPK2(s0, s1, sA2);
            float qA = q0 + q1, sA = s0 + s1;
            UNPK2(q0, q1, qB2); UNPK2(s0, s1, sB2);
            float qB = q0 + q1, sB = s0 + s1;
            qA += __shfl_xor_sync(0xffffffffu, qA, 1);
            qA += __shfl_xor_sync(0xffffffffu, qA, 2);
            sA += __shfl_xor_sync(0xffffffffu, sA, 1);
            sA += __shfl_xor_sync(0xffffffffu, sA, 2);
            qB += __shfl_xor_sync(0xffffffffu, qB, 1);
            qB += __shfl_xor_sync(0xffffffffu, qB, 2);
            sB += __shfl_xor_sync(0xffffffffu, sB, 1);
            sB += __shfl_xor_sync(0xffffffffu, sB, 2);
            tauA += __fdividef(qA - 4.0f, 4.0f * sA);
            tauB += __fdividef(qB - 4.0f, 4.0f * sB);
        }

        // ---- final p = r'^2 (scale cancels in normalization), psum, inv ----
        {
            unsigned long long nA2, nB2, pA2 = 0ULL, pB2 = 0ULL;
            float ntA = -tauA, ntB = -tauB;
            PACK2(nA2, ntA, ntA);
            PACK2(nB2, ntB, ntB);
#pragma unroll
            for (int t = 0; t < 16; t++) {
                unsigned long long t2, r2, p2;
                ADD2(t2, zA[t], nA2);
                r2 = t2 & ABSM;
                ADD2(r2, t2, r2);
                MUL2(p2, r2, r2);
                zA[t] = p2;
                ADD2(pA2, pA2, p2);
                ADD2(t2, zB[t], nB2);
                r2 = t2 & ABSM;
                ADD2(r2, t2, r2);
                MUL2(p2, r2, r2);
                zB[t] = p2;
                ADD2(pB2, pB2, p2);
            }
            float p0, p1;
            UNPK2(p0, p1, pA2); float psA = p0 + p1;
            UNPK2(p0, p1, pB2); float psB = p0 + p1;
            psA += __shfl_xor_sync(0xffffffffu, psA, 1);
            psA += __shfl_xor_sync(0xffffffffu, psA, 2);
            psB += __shfl_xor_sync(0xffffffffu, psB, 1);
            psB += __shfl_xor_sync(0xffffffffu, psB, 2);
            const float invA = __fdividef(1.0f, psA);
            const float invB = __fdividef(1.0f, psB);

            // ---- half 0: rows 0..63 (head 2hp), warps 0-3 ----
            __syncthreads();
            if (wid < 4) {
#pragma unroll
                for (int t = 0; t < 16; t++) {
                    int col = t * 8 + 2 * tg;
                    float f0, f1;
                    UNPK2(f0, f1, zA[t]);
                    *(float2*)(att + rowA * ASTRIDE + col) = make_float2(f0 * invA, f1 * invA);
                    UNPK2(f0, f1, zB[t]);
                    *(float2*)(att + rowB * ASTRIDE + col) = make_float2(f0 * invB, f1 * invB);
                }
            }
            __syncthreads();
#pragma unroll
            for (int it = 0; it < 8; it++) {
                const int r = it * 8 + wid;
                float4 a = *(const float4*)(att + r * ASTRIDE + lane * 4);
                float4 v = V4[(hp * 128 + r) * 32 + lane];
                float4 w;
                w.x = a.x * v.x; w.y = a.y * v.y; w.z = a.z * v.z; w.w = a.w * v.w;
                O4[(((size_t)b * KH + hp * 2) * O_ + r) * 32 + lane] = w;
            }
            __syncthreads();

            // ---- half 1: rows 64..127 (head 2hp+1), warps 4-7 ----
            if (wid >= 4) {
#pragma unroll
                for (int t = 0; t < 16; t++) {
                    int col = t * 8 + 2 * tg;
                    float f0, f1;
                    UNPK2(f0, f1, zA[t]);
                    *(float2*)(att + (rowA - 64) * ASTRIDE + col) = make_float2(f0 * invA, f1 * invA);
                    UNPK2(f0, f1, zB[t]);
                    *(float2*)(att + (rowB - 64) * ASTRIDE + col) = make_float2(f0 * invB, f1 * invB);
                }
            }
            __syncthreads();
#pragma unroll
            for (int it = 0; it < 8; it++) {
                const int r = it * 8 + wid;
                float4 a = *(const float4*)(att + r * ASTRIDE + lane * 4);
                float4 v = V4[(hp * 128 + 64 + r) * 32 + lane];
                float4 w;
                w.x = a.x * v.x; w.y = a.y * v.y; w.z = a.z * v.z; w.w = a.w * v.w;
                O4[(((size_t)b * KH + hp * 2 + 1) * O_ + r) * 32 + lane] = w;
            }
            __syncthreads();
        }
    }
}

// ---------------------------------------------------------------------------
extern "C" void kernel_launch(void* const* d_in, const int* in_sizes, int n_in,
                              void* d_out, int out_size) {
    const float* x = (const float*)d_in[0];   // [2048,128,128]
    const float* w = (const float*)d_in[1];   // [8,128,64]
    const float* q = (const float*)d_in[2];   // [8,64,64]
    const float* v = (const float*)d_in[3];   // [8,64,128]
    float* out = (float*)d_out;               // [2048,8,64,128]

    cudaFuncSetAttribute(main_kernel, cudaFuncAttributeMaxDynamicSharedMemorySize, SM_TOTAL);

    prep_kernel<<<64, 256>>>(w, q);
    main_kernel<<<B_, 256, SM_TOTAL>>>(x, v, out);
}

// round 11
// speedup vs baseline: 2.3056x; 1.1144x over previous
#include <cuda_runtime.h>
#include <cuda_bf16.h>
#include <cstdint>

#define B_   2048
#define F_   128
#define E_   128
#define KH   8
#define O_   64
#define FOLD 0.0625f     // (alpha-1) * d_k^-0.5 folded into C
#define NIT  6           // Newton iterations (packed) — 5 is NOT enough (R9: 3.1e-3)

// ---------------- device scratch ----------------
// A in MMA-fragment order: [hp][wid][kt][lane][reg0..3] u32  (one uint4 per lane per kt)
__device__ __align__(16) uint32_t g_FH[4 * 8 * 8 * 32 * 4];   // 128 KB (hi)
__device__ __align__(16) uint32_t g_FL[4 * 8 * 8 * 32 * 4];   // 128 KB (lo)

// smem: Xh [128][272B] + Xl [128][272B] (persist) + per-warp buf 8x132 f32 x 8 warps
#define XSTRIDE 272
#define XLOFF   (128 * XSTRIDE)
#define ATT_OFF (2 * 128 * XSTRIDE)          // 69632
#define WBUF_FLOATS (8 * 132)                // per-warp: 8 rows x 132
#define SM_TOTAL (ATT_OFF + 8 * WBUF_FLOATS * 4)   // 69632 + 33792 = 103424 B

__device__ __forceinline__ uint32_t smem_u32(const void* p) {
    uint32_t a;
    asm("{ .reg .u64 t; cvta.to.shared.u64 t, %1; cvt.u32.u64 %0, t; }" : "=r"(a) : "l"(p));
    return a;
}

__device__ __forceinline__ void mma_bf16(float* d, const uint4& a,
                                         uint32_t b0, uint32_t b1) {
    asm volatile("mma.sync.aligned.m16n8k16.row.col.f32.bf16.bf16.f32 "
                 "{%0,%1,%2,%3}, {%4,%5,%6,%7}, {%8,%9}, {%0,%1,%2,%3};"
                 : "+f"(d[0]), "+f"(d[1]), "+f"(d[2]), "+f"(d[3])
                 : "r"(a.x), "r"(a.y), "r"(a.z), "r"(a.w), "r"(b0), "r"(b1));
}

__device__ __forceinline__ void ldmx4(uint32_t& b0, uint32_t& b1, uint32_t& b2, uint32_t& b3,
                                      uint32_t addr) {
    asm volatile("ldmatrix.sync.aligned.m8n8.x4.shared.b16 {%0,%1,%2,%3}, [%4];"
                 : "=r"(b0), "=r"(b1), "=r"(b2), "=r"(b3) : "r"(addr));
}

// packed f32x2 helpers (base Blackwell ISA)
#define ADD2(d, a, b)  asm("add.rn.f32x2 %0, %1, %2;" : "=l"(d) : "l"(a), "l"(b))
#define MUL2(d, a, b)  asm("mul.rn.f32x2 %0, %1, %2;" : "=l"(d) : "l"(a), "l"(b))
#define FMA2ACC(d, a, b) asm("fma.rn.f32x2 %0, %1, %2, %0;" : "+l"(d) : "l"(a), "l"(b))
#define PACK2(d, lo, hi) asm("mov.b64 %0, {%1, %2};" : "=l"(d) : "f"(lo), "f"(hi))
#define UNPK2(lo, hi, s) asm("mov.b64 {%0, %1}, %2;" : "=f"(lo), "=f"(hi) : "l"(s))
#define ABSM 0x7fffffff7fffffffULL

// ---------------------------------------------------------------------------
// prep: C = FOLD * W*Q^T per head, bf16 hi/lo split, stored in fragment order
// ---------------------------------------------------------------------------
#define QS_STRIDE 65
__global__ __launch_bounds__(256)
void prep_kernel(const float* __restrict__ W, const float* __restrict__ Q) {
    __shared__ float qs[64 * QS_STRIDE];   // [o][y], padded
    __shared__ float ws[16 * 64];          // [xl][y]
    const int tid = threadIdx.x;
    const int k   = blockIdx.x >> 3;
    const int x0  = (blockIdx.x & 7) * 16;

    for (int i = tid; i < 4096; i += 256)
        qs[(i >> 6) * QS_STRIDE + (i & 63)] = Q[k * 4096 + i];
    for (int i = tid; i < 1024; i += 256)
        ws[i] = W[(k * 128 + x0) * 64 + i];
    __syncthreads();

    const int hp = k >> 1;
    const int mb = (k & 1) * 64;
#pragma unroll
    for (int j = 0; j < 4; j++) {
        int xo = tid + j * 256;
        int xl = xo >> 6, o = xo & 63;
        const float* wr = ws + xl * 64;
        const float* qr = qs + o * QS_STRIDE;
        float acc = 0.0f;
#pragma unroll
        for (int y = 0; y < 64; y++) acc = fmaf(wr[y], qr[y], acc);
        acc *= FOLD;
        __nv_bfloat16 h = __float2bfloat16(acc);
        __nv_bfloat16 l = __float2bfloat16(acc - __bfloat162float(h));

        const int m   = mb + o;
        const int x   = x0 + xl;
        const int wid = m >> 4, g = m & 7, pA = (m >> 3) & 1;
        const int kt  = x >> 4, xr = x & 15;
        const int hi8 = (xr >> 3) & 1, tg = (xr >> 1) & 3, half = x & 1;
        const int r    = pA + 2 * hi8;
        const int lane = g * 4 + tg;
        const int idx2 = ((((hp * 8 + wid) * 8 + kt) * 32 + lane) * 4 + r) * 2 + half;
        ((__nv_bfloat16*)g_FH)[idx2] = h;
        ((__nv_bfloat16*)g_FL)[idx2] = l;
    }
}

// ---------------------------------------------------------------------------
// main: one CTA per b; stage X once, loop 4 head-pairs with NO CTA barriers:
//       HMMA 3-term GEMM -> entmax-1.5 (packed Newton, moment trick) -> *values
//       (warp-local transpose epilogue -> warps drift -> pipe overlap)
// ---------------------------------------------------------------------------
__global__ __launch_bounds__(256, 2)
void main_kernel(const float* __restrict__ Xg, const float* __restrict__ Vg,
                 float* __restrict__ out) {
    extern __shared__ char smem[];
    const int tid  = threadIdx.x;
    const int wid  = tid >> 5;
    const int lane = tid & 31;
    const int b    = blockIdx.x;
    const int mw   = wid * 16;

    // ---- stage X[b]: fp32 -> bf16 hi/lo into smem (once per b) ----
    {
        const float4* Xb4 = (const float4*)(Xg + (size_t)b * F_ * E_);
#pragma unroll
        for (int i = tid; i < 4096; i += 256) {
            int row = i >> 5, c = i & 31;
            float4 v = Xb4[i];
            uint2 hi, lo;
            __nv_bfloat16 h0 = __float2bfloat16(v.x), h1 = __float2bfloat16(v.y);
            __nv_bfloat16 h2 = __float2bfloat16(v.z), h3 = __float2bfloat16(v.w);
            __nv_bfloat162 p01{h0, h1}, p23{h2, h3};
            hi.x = *(uint32_t*)&p01; hi.y = *(uint32_t*)&p23;
            __nv_bfloat162 l01{__float2bfloat16(v.x - __bfloat162float(h0)),
                               __float2bfloat16(v.y - __bfloat162float(h1))};
            __nv_bfloat162 l23{__float2bfloat16(v.z - __bfloat162float(h2)),
                               __float2bfloat16(v.w - __bfloat162float(h3))};
            lo.x = *(uint32_t*)&l01; lo.y = *(uint32_t*)&l23;
            *(uint2*)(smem + row * XSTRIDE + c * 8)         = hi;
            *(uint2*)(smem + XLOFF + row * XSTRIDE + c * 8) = lo;
        }
    }
    __syncthreads();   // only CTA-wide barrier; X is read-only afterwards

    const int g  = lane >> 2;
    const int tg = lane & 3;
    const int ln  = (lane & 7) + ((lane >> 4) << 3);
    const int lk8 = (lane >> 3) & 1;
    const uint32_t sbase = smem_u32(smem);
    float* wbuf = (float*)(smem + ATT_OFF) + wid * WBUF_FLOATS;   // warp-private
    const float4* V4 = (const float4*)Vg;
    float4* O4 = (float4*)out;

#pragma unroll 1
    for (int hp = 0; hp < 4; hp++) {
        // ---- MMA mainloop ----
        float acc[16][4];
#pragma unroll
        for (int t = 0; t < 16; t++)
#pragma unroll
            for (int j = 0; j < 4; j++) acc[t][j] = 0.0f;

        const uint4* FH4 = ((const uint4*)g_FH) + ((hp * 8 + wid) * 8) * 32 + lane;
        const uint4* FL4 = ((const uint4*)g_FL) + ((hp * 8 + wid) * 8) * 32 + lane;

        uint4 ah = FH4[0];
        uint4 al = FL4[0];
#pragma unroll
        for (int kt = 0; kt < 8; kt++) {
            const int ktn = (kt < 7) ? kt + 1 : 7;
            uint4 ahn = FH4[ktn * 32];
            uint4 aln = FL4[ktn * 32];
            uint32_t raddr = sbase + (uint32_t)(ln * XSTRIDE + (kt * 2 + lk8) * 16);
#pragma unroll
            for (int j = 0; j < 4; j++) {
                uint32_t r0a = raddr + (uint32_t)((2 * j) * 16 * XSTRIDE);
                uint32_t r1a = raddr + (uint32_t)((2 * j + 1) * 16 * XSTRIDE);
                uint32_t b0, b1, b2, b3, c0, c1, c2, c3;
                uint32_t lb0, lb1, lb2, lb3, lc0, lc1, lc2, lc3;
                ldmx4(b0, b1, b2, b3, r0a);
                ldmx4(lb0, lb1, lb2, lb3, r0a + (uint32_t)XLOFF);
                ldmx4(c0, c1, c2, c3, r1a);
                ldmx4(lc0, lc1, lc2, lc3, r1a + (uint32_t)XLOFF);
                float* A0 = acc[4 * j];
                float* A1 = acc[4 * j + 1];
                float* A2 = acc[4 * j + 2];
                float* A3 = acc[4 * j + 3];
                mma_bf16(A0, ah, b0, b1);
                mma_bf16(A1, ah, b2, b3);
                mma_bf16(A2, ah, c0, c1);
                mma_bf16(A3, ah, c2, c3);
                mma_bf16(A0, ah, lb0, lb1);
                mma_bf16(A1, ah, lb2, lb3);
                mma_bf16(A2, ah, lc0, lc1);
                mma_bf16(A3, ah, lc2, lc3);
                mma_bf16(A0, al, b0, b1);
                mma_bf16(A1, al, b2, b3);
                mma_bf16(A2, al, c0, c1);
                mma_bf16(A3, al, c2, c3);
            }
            ah = ahn;
            al = aln;
        }

        // ---- row max (warp-local) ----
        float mA = acc[0][0], mB = acc[0][2];
#pragma unroll
        for (int t = 0; t < 16; t++) {
            mA = fmaxf(mA, fmaxf(acc[t][0], acc[t][1]));
            mB = fmaxf(mB, fmaxf(acc[t][2], acc[t][3]));
        }
        mA = fmaxf(mA, __shfl_xor_sync(0xffffffffu, mA, 1));
        mA = fmaxf(mA, __shfl_xor_sync(0xffffffffu, mA, 2));
        mB = fmaxf(mB, __shfl_xor_sync(0xffffffffu, mB, 1));
        mB = fmaxf(mB, __shfl_xor_sync(0xffffffffu, mB, 2));

        // ---- pack z into f32x2 + row moments S=Σz, Q=Σz² (once per row) ----
        unsigned long long zA[16], zB[16];
        unsigned long long SA2 = 0, QA2 = 0, SB2 = 0, QB2 = 0;
#pragma unroll
        for (int t = 0; t < 16; t++) {
            PACK2(zA[t], acc[t][0], acc[t][1]);
            PACK2(zB[t], acc[t][2], acc[t][3]);
            ADD2(SA2, SA2, zA[t]);
            FMA2ACC(QA2, zA[t], zA[t]);
            ADD2(SB2, SB2, zB[t]);
            FMA2ACC(QB2, zB[t], zB[t]);
        }
        float SAll_A, QAll_A, SAll_B, QAll_B;
        {
            float a0, a1;
            UNPK2(a0, a1, SA2); SAll_A = a0 + a1;
            UNPK2(a0, a1, QA2); QAll_A = a0 + a1;
            UNPK2(a0, a1, SB2); SAll_B = a0 + a1;
            UNPK2(a0, a1, QB2); QAll_B = a0 + a1;
            SAll_A += __shfl_xor_sync(0xffffffffu, SAll_A, 1);
            SAll_A += __shfl_xor_sync(0xffffffffu, SAll_A, 2);
            QAll_A += __shfl_xor_sync(0xffffffffu, QAll_A, 1);
            QAll_A += __shfl_xor_sync(0xffffffffu, QAll_A, 2);
            SAll_B += __shfl_xor_sync(0xffffffffu, SAll_B, 1);
            SAll_B += __shfl_xor_sync(0xffffffffu, SAll_B, 2);
            QAll_B += __shfl_xor_sync(0xffffffffu, QAll_B, 1);
            QAll_B += __shfl_xor_sync(0xffffffffu, QAll_B, 2);
        }

        float tauA = mA - 1.0f, tauB = mB - 1.0f;

        // ---- packed Newton via moments: per elem only T += t|t|, Sb += |t| ----
        // Σr'² = 2(Q − 2τS + 128τ²) + 2T ;  Σr' = (S − 128τ) + Σ|t| ; r' = 2r
#pragma unroll 1
        for (int it = 0; it < NIT; it++) {
            unsigned long long nA2, nB2;
            unsigned long long TA2 = 0, SbA2 = 0, TB2 = 0, SbB2 = 0;
            float ntA = -tauA, ntB = -tauB;
            PACK2(nA2, ntA, ntA);
            PACK2(nB2, ntB, ntB);
#pragma unroll
            for (int t = 0; t < 16; t++) {
                unsigned long long t2, a2;
                ADD2(t2, zA[t], nA2);
                a2 = t2 & ABSM;
                FMA2ACC(TA2, t2, a2);
                ADD2(SbA2, SbA2, a2);
                ADD2(t2, zB[t], nB2);
                a2 = t2 & ABSM;
                FMA2ACC(TB2, t2, a2);
                ADD2(SbB2, SbB2, a2);
            }
            float x0, x1;
            UNPK2(x0, x1, TA2);  float TA  = x0 + x1;
            UNPK2(x0, x1, SbA2); float SbA = x0 + x1;
            UNPK2(x0, x1, TB2);  float TB  = x0 + x1;
            UNPK2(x0, x1, SbB2); float SbB = x0 + x1;
            TA  += __shfl_xor_sync(0xffffffffu, TA, 1);
            TA  += __shfl_xor_sync(0xffffffffu, TA, 2);
            SbA += __shfl_xor_sync(0xffffffffu, SbA, 1);
            SbA += __shfl_xor_sync(0xffffffffu, SbA, 2);
            TB  += __shfl_xor_sync(0xffffffffu, TB, 1);
            TB  += __shfl_xor_sync(0xffffffffu, TB, 2);
            SbB += __shfl_xor_sync(0xffffffffu, SbB, 1);
            SbB += __shfl_xor_sync(0xffffffffu, SbB, 2);
            float sA = fmaf(-128.0f, tauA, SAll_A) + SbA;
            float qA = 2.0f * fmaf(fmaf(128.0f, tauA, -2.0f * SAll_A), tauA, QAll_A) + 2.0f * TA;
            float sB = fmaf(-128.0f, tauB, SAll_B) + SbB;
            float qB = 2.0f * fmaf(fmaf(128.0f, tauB, -2.0f * SAll_B), tauB, QAll_B) + 2.0f * TB;
            tauA += __fdividef(qA - 4.0f, 4.0f * sA);
            tauB += __fdividef(qB - 4.0f, 4.0f * sB);
        }

        // ---- final p = r'^2 (scale cancels), psum, inv ----
        float invA, invB;
        {
            unsigned long long nA2, nB2, pA2 = 0ULL, pB2 = 0ULL;
            float ntA = -tauA, ntB = -tauB;
            PACK2(nA2, ntA, ntA);
            PACK2(nB2, ntB, ntB);
#pragma unroll
            for (int t = 0; t < 16; t++) {
                unsigned long long t2, r2, p2;
                ADD2(t2, zA[t], nA2);
                r2 = t2 & ABSM;
                ADD2(r2, t2, r2);
                MUL2(p2, r2, r2);
                zA[t] = p2;
                ADD2(pA2, pA2, p2);
                ADD2(t2, zB[t], nB2);
                r2 = t2 & ABSM;
                ADD2(r2, t2, r2);
                MUL2(p2, r2, r2);
                zB[t] = p2;
                ADD2(pB2, pB2, p2);
            }
            float p0, p1;
            UNPK2(p0, p1, pA2); float psA = p0 + p1;
            UNPK2(p0, p1, pB2); float psB = p0 + p1;
            psA += __shfl_xor_sync(0xffffffffu, psA, 1);
            psA += __shfl_xor_sync(0xffffffffu, psA, 2);
            psB += __shfl_xor_sync(0xffffffffu, psB, 1);
            psB += __shfl_xor_sync(0xffffffffu, psB, 2);
            invA = __fdividef(1.0f, psA);
            invB = __fdividef(1.0f, psB);
        }

        // ---- warp-local transpose + store, chunk 0 (rows mw..mw+7, zA) ----
#pragma unroll
        for (int t = 0; t < 16; t++) {
            float f0, f1;
            UNPK2(f0, f1, zA[t]);
            *(float2*)(wbuf + g * 132 + t * 8 + 2 * tg) = make_float2(f0 * invA, f1 * invA);
        }
        __syncwarp();
#pragma unroll
        for (int r8 = 0; r8 < 8; r8++) {
            const int row = mw + r8;                 // 0..127
            float4 a = *(const float4*)(wbuf + r8 * 132 + lane * 4);
            float4 v = V4[(hp * 128 + row) * 32 + lane];
            const int kk = hp * 2 + (row >> 6), o = row & 63;
            float4 w;
            w.x = a.x * v.x; w.y = a.y * v.y; w.z = a.z * v.z; w.w = a.w * v.w;
            O4[(((size_t)b * KH + kk) * O_ + o) * 32 + lane] = w;
        }
        __syncwarp();

        // ---- chunk 1 (rows mw+8..mw+15, zB) ----
#pragma unroll
        for (int t = 0; t < 16; t++) {
            float f0, f1;
            UNPK2(f0, f1, zB[t]);
            *(float2*)(wbuf + g * 132 + t * 8 + 2 * tg) = make_float2(f0 * invB, f1 * invB);
        }
        __syncwarp();
#pragma unroll
        for (int r8 = 0; r8 < 8; r8++) {
            const int row = mw + 8 + r8;             // 0..127
            float4 a = *(const float4*)(wbuf + r8 * 132 + lane * 4);
            float4 v = V4[(hp * 128 + row) * 32 + lane];
            const int kk = hp * 2 + (row >> 6), o = row & 63;
            float4 w;
            w.x = a.x * v.x; w.y = a.y * v.y; w.z = a.z * v.z; w.w = a.w * v.w;
            O4[(((size_t)b * KH + kk) * O_ + o) * 32 + lane] = w;
        }
        __syncwarp();
    }
}

// ---------------------------------------------------------------------------
extern "C" void kernel_launch(void* const* d_in, const int* in_sizes, int n_in,
                              void* d_out, int out_size) {
    const float* x = (const float*)d_in[0];   // [2048,128,128]
    const float* w = (const float*)d_in[1];   // [8,128,64]
    const float* q = (const float*)d_in[2];   // [8,64,64]
    const float* v = (const float*)d_in[3];   // [8,64,128]
    float* out = (float*)d_out;               // [2048,8,64,128]

    cudaFuncSetAttribute(main_kernel, cudaFuncAttributeMaxDynamicSharedMemorySize, SM_TOTAL);

    prep_kernel<<<64, 256>>>(w, q);
    main_kernel<<<B_, 256, SM_TOTAL>>>(x, v, out);
}

// round 13
// speedup vs baseline: 2.3679x; 1.0270x over previous
#include <cuda_runtime.h>
#include <cuda_bf16.h>
#include <cstdint>

#define B_   2048
#define F_   128
#define E_   128
#define KH   8
#define O_   64
#define FOLD 0.0625f     // (alpha-1) * d_k^-0.5 folded into C
#define NIT  5           // Newton iterations (with moment-based smart init)

// ---------------- device scratch ----------------
// A in MMA-fragment order: [hp][wid][kt][lane][reg0..3] u32  (one uint4 per lane per kt)
__device__ __align__(16) uint32_t g_FH[4 * 8 * 8 * 32 * 4];   // 128 KB (hi)
__device__ __align__(16) uint32_t g_FL[4 * 8 * 8 * 32 * 4];   // 128 KB (lo)

// hp stride in uint4 units: 8 wids * 8 kts * 32 lanes
#define HP_STRIDE_U4 (8 * 8 * 32)

// smem: Xh [128][272B] + Xl [128][272B] (persist) + per-warp buf 8x132 f32 x 8 warps
#define XSTRIDE 272
#define XLOFF   (128 * XSTRIDE)
#define ATT_OFF (2 * 128 * XSTRIDE)          // 69632
#define WBUF_FLOATS (8 * 132)                // per-warp: 8 rows x 132
#define SM_TOTAL (ATT_OFF + 8 * WBUF_FLOATS * 4)   // 103424 B

__device__ __forceinline__ uint32_t smem_u32(const void* p) {
    uint32_t a;
    asm("{ .reg .u64 t; cvta.to.shared.u64 t, %1; cvt.u32.u64 %0, t; }" : "=r"(a) : "l"(p));
    return a;
}

__device__ __forceinline__ void mma_bf16(float* d, const uint4& a,
                                         uint32_t b0, uint32_t b1) {
    asm volatile("mma.sync.aligned.m16n8k16.row.col.f32.bf16.bf16.f32 "
                 "{%0,%1,%2,%3}, {%4,%5,%6,%7}, {%8,%9}, {%0,%1,%2,%3};"
                 : "+f"(d[0]), "+f"(d[1]), "+f"(d[2]), "+f"(d[3])
                 : "r"(a.x), "r"(a.y), "r"(a.z), "r"(a.w), "r"(b0), "r"(b1));
}

__device__ __forceinline__ void ldmx4(uint32_t& b0, uint32_t& b1, uint32_t& b2, uint32_t& b3,
                                      uint32_t addr) {
    asm volatile("ldmatrix.sync.aligned.m8n8.x4.shared.b16 {%0,%1,%2,%3}, [%4];"
                 : "=r"(b0), "=r"(b1), "=r"(b2), "=r"(b3) : "r"(addr));
}

// packed f32x2 helpers (base Blackwell ISA)
#define ADD2(d, a, b)  asm("add.rn.f32x2 %0, %1, %2;" : "=l"(d) : "l"(a), "l"(b))
#define MUL2(d, a, b)  asm("mul.rn.f32x2 %0, %1, %2;" : "=l"(d) : "l"(a), "l"(b))
#define FMA2ACC(d, a, b) asm("fma.rn.f32x2 %0, %1, %2, %0;" : "+l"(d) : "l"(a), "l"(b))
#define PACK2(d, lo, hi) asm("mov.b64 %0, {%1, %2};" : "=l"(d) : "f"(lo), "f"(hi))
#define UNPK2(lo, hi, s) asm("mov.b64 {%0, %1}, %2;" : "=f"(lo), "=f"(hi) : "l"(s))
#define ABSM 0x7fffffff7fffffffULL

// ---------------------------------------------------------------------------
// prep: C = FOLD * W*Q^T per head, bf16 hi/lo split, fragment order
// grid = 256 blocks (k, x-chunk of 4), 256 threads, 1 item/thread
// ---------------------------------------------------------------------------
#define QS_STRIDE 65
__global__ __launch_bounds__(256)
void prep_kernel(const float* __restrict__ W, const float* __restrict__ Q) {
    __shared__ float qs[64 * QS_STRIDE];   // [o][y], padded
    __shared__ float ws[4 * 64];           // [xl][y]
    const int tid = threadIdx.x;
    const int k   = blockIdx.x >> 5;
    const int x0  = (blockIdx.x & 31) * 4;

    for (int i = tid; i < 4096; i += 256)
        qs[(i >> 6) * QS_STRIDE + (i & 63)] = Q[k * 4096 + i];
    ws[tid] = W[(k * 128 + x0) * 64 + tid];
    __syncthreads();

    const int hp = k >> 1;
    const int mb = (k & 1) * 64;
    {
        int xl = tid >> 6, o = tid & 63;
        const float* wr = ws + xl * 64;
        const float* qr = qs + o * QS_STRIDE;
        float acc = 0.0f;
#pragma unroll
        for (int y = 0; y < 64; y++) acc = fmaf(wr[y], qr[y], acc);
        acc *= FOLD;
        __nv_bfloat16 h = __float2bfloat16(acc);
        __nv_bfloat16 l = __float2bfloat16(acc - __bfloat162float(h));

        const int m   = mb + o;
        const int x   = x0 + xl;
        const int wid = m >> 4, g = m & 7, pA = (m >> 3) & 1;
        const int kt  = x >> 4, xr = x & 15;
        const int hi8 = (xr >> 3) & 1, tg = (xr >> 1) & 3, half = x & 1;
        const int r    = pA + 2 * hi8;
        const int lane = g * 4 + tg;
        const int idx2 = ((((hp * 8 + wid) * 8 + kt) * 32 + lane) * 4 + r) * 2 + half;
        ((__nv_bfloat16*)g_FH)[idx2] = h;
        ((__nv_bfloat16*)g_FL)[idx2] = l;
    }
}

// ---------------------------------------------------------------------------
// main: one CTA per b; stage X once, loop 4 head-pairs with NO CTA barriers
// ---------------------------------------------------------------------------
__global__ __launch_bounds__(256, 2)
void main_kernel(const float* __restrict__ Xg, const float* __restrict__ Vg,
                 float* __restrict__ out) {
    extern __shared__ char smem[];
    const int tid  = threadIdx.x;
    const int wid  = tid >> 5;
    const int lane = tid & 31;
    const int b    = blockIdx.x;
    const int mw   = wid * 16;

    // ---- stage X[b]: fp32 -> bf16 hi/lo into smem (once per b) ----
    {
        const float4* Xb4 = (const float4*)(Xg + (size_t)b * F_ * E_);
#pragma unroll
        for (int i = tid; i < 4096; i += 256) {
            int row = i >> 5, c = i & 31;
            float4 v = Xb4[i];
            uint2 hi, lo;
            __nv_bfloat16 h0 = __float2bfloat16(v.x), h1 = __float2bfloat16(v.y);
            __nv_bfloat16 h2 = __float2bfloat16(v.z), h3 = __float2bfloat16(v.w);
            __nv_bfloat162 p01{h0, h1}, p23{h2, h3};
            hi.x = *(uint32_t*)&p01; hi.y = *(uint32_t*)&p23;
            __nv_bfloat162 l01{__float2bfloat16(v.x - __bfloat162float(h0)),
                               __float2bfloat16(v.y - __bfloat162float(h1))};
            __nv_bfloat162 l23{__float2bfloat16(v.z - __bfloat162float(h2)),
                               __float2bfloat16(v.w - __bfloat162float(h3))};
            lo.x = *(uint32_t*)&l01; lo.y = *(uint32_t*)&l23;
            *(uint2*)(smem + row * XSTRIDE + c * 8)         = hi;
            *(uint2*)(smem + XLOFF + row * XSTRIDE + c * 8) = lo;
        }
    }
    __syncthreads();   // only CTA-wide barrier; X is read-only afterwards

    const int g  = lane >> 2;
    const int tg = lane & 3;
    const int ln  = (lane & 7) + ((lane >> 4) << 3);
    const int lk8 = (lane >> 3) & 1;
    const uint32_t sbase = smem_u32(smem);
    float* wbuf = (float*)(smem + ATT_OFF) + wid * WBUF_FLOATS;   // warp-private
    const float4* V4 = (const float4*)Vg;
    float4* O4 = (float4*)out;

    // rolling A-fragment registers (prefetched across hp boundary)
    const uint4* FH4 = ((const uint4*)g_FH) + (wid * 8) * 32 + lane;   // hp=0 base
    const uint4* FL4 = ((const uint4*)g_FL) + (wid * 8) * 32 + lane;
    uint4 ah = FH4[0];
    uint4 al = FL4[0];

#pragma unroll 1
    for (int hp = 0; hp < 4; hp++) {
        // ---- MMA mainloop (ah/al enter preloaded with kt0 of this hp) ----
        float acc[16][4];
#pragma unroll
        for (int t = 0; t < 16; t++)
#pragma unroll
            for (int j = 0; j < 4; j++) acc[t][j] = 0.0f;

#pragma unroll
        for (int kt = 0; kt < 8; kt++) {
            const int ktn = (kt < 7) ? kt + 1 : 7;
            uint4 ahn = FH4[ktn * 32];
            uint4 aln = FL4[ktn * 32];
            uint32_t raddr = sbase + (uint32_t)(ln * XSTRIDE + (kt * 2 + lk8) * 16);
#pragma unroll
            for (int j = 0; j < 4; j++) {
                uint32_t r0a = raddr + (uint32_t)((2 * j) * 16 * XSTRIDE);
                uint32_t r1a = raddr + (uint32_t)((2 * j + 1) * 16 * XSTRIDE);
                uint32_t b0, b1, b2, b3, c0, c1, c2, c3;
                uint32_t lb0, lb1, lb2, lb3, lc0, lc1, lc2, lc3;
                ldmx4(b0, b1, b2, b3, r0a);
                ldmx4(lb0, lb1, lb2, lb3, r0a + (uint32_t)XLOFF);
                ldmx4(c0, c1, c2, c3, r1a);
                ldmx4(lc0, lc1, lc2, lc3, r1a + (uint32_t)XLOFF);
                float* A0 = acc[4 * j];
                float* A1 = acc[4 * j + 1];
                float* A2 = acc[4 * j + 2];
                float* A3 = acc[4 * j + 3];
                mma_bf16(A0, ah, b0, b1);
                mma_bf16(A1, ah, b2, b3);
                mma_bf16(A2, ah, c0, c1);
                mma_bf16(A3, ah, c2, c3);
                mma_bf16(A0, ah, lb0, lb1);
                mma_bf16(A1, ah, lb2, lb3);
                mma_bf16(A2, ah, lc0, lc1);
                mma_bf16(A3, ah, lc2, lc3);
                mma_bf16(A0, al, b0, b1);
                mma_bf16(A1, al, b2, b3);
                mma_bf16(A2, al, c0, c1);
                mma_bf16(A3, al, c2, c3);
            }
            ah = ahn;
            al = aln;
        }

        // ---- prefetch next hp's kt0 A-fragments (hidden under Newton) ----
        // hp stride = 8 wids * 8 kts * 32 lanes uint4s  (R12 bug: used 8*32)
        if (hp < 3) {
            FH4 += HP_STRIDE_U4;
            FL4 += HP_STRIDE_U4;
            ah = FH4[0];
            al = FL4[0];
        }

        // ---- row max (warp-local) ----
        float mA = acc[0][0], mB = acc[0][2];
#pragma unroll
        for (int t = 0; t < 16; t++) {
            mA = fmaxf(mA, fmaxf(acc[t][0], acc[t][1]));
            mB = fmaxf(mB, fmaxf(acc[t][2], acc[t][3]));
        }
        mA = fmaxf(mA, __shfl_xor_sync(0xffffffffu, mA, 1));
        mA = fmaxf(mA, __shfl_xor_sync(0xffffffffu, mA, 2));
        mB = fmaxf(mB, __shfl_xor_sync(0xffffffffu, mB, 1));
        mB = fmaxf(mB, __shfl_xor_sync(0xffffffffu, mB, 2));

        // ---- pack z into f32x2 + row moments S=Σz, Q=Σz² ----
        unsigned long long zA[16], zB[16];
        unsigned long long SA2 = 0, QA2 = 0, SB2 = 0, QB2 = 0;
#pragma unroll
        for (int t = 0; t < 16; t++) {
            PACK2(zA[t], acc[t][0], acc[t][1]);
            PACK2(zB[t], acc[t][2], acc[t][3]);
            ADD2(SA2, SA2, zA[t]);
            FMA2ACC(QA2, zA[t], zA[t]);
            ADD2(SB2, SB2, zB[t]);
            FMA2ACC(QB2, zB[t], zB[t]);
        }
        float SAll_A, QAll_A, SAll_B, QAll_B;
        {
            float a0, a1;
            UNPK2(a0, a1, SA2); SAll_A = a0 + a1;
            UNPK2(a0, a1, QA2); QAll_A = a0 + a1;
            UNPK2(a0, a1, SB2); SAll_B = a0 + a1;
            UNPK2(a0, a1, QB2); QAll_B = a0 + a1;
            SAll_A += __shfl_xor_sync(0xffffffffu, SAll_A, 1);
            SAll_A += __shfl_xor_sync(0xffffffffu, SAll_A, 2);
            QAll_A += __shfl_xor_sync(0xffffffffu, QAll_A, 1);
            QAll_A += __shfl_xor_sync(0xffffffffu, QAll_A, 2);
            SAll_B += __shfl_xor_sync(0xffffffffu, SAll_B, 1);
            SAll_B += __shfl_xor_sync(0xffffffffu, SAll_B, 2);
            QAll_B += __shfl_xor_sync(0xffffffffu, QAll_B, 1);
            QAll_B += __shfl_xor_sync(0xffffffffu, QAll_B, 2);
        }

        // ---- smart init: all-support closed form, clamped to safe bracket ----
        float tauA, tauB;
        {
            float DA = fmaxf(fmaf(SAll_A, SAll_A, -128.0f * (QAll_A - 1.0f)), 0.0f);
            float tqA = (SAll_A - sqrtf(DA)) * 0.0078125f;
            tauA = fmaxf(mA - 1.0f, fminf(tqA, mA - 0.0078125f));
            float DB = fmaxf(fmaf(SAll_B, SAll_B, -128.0f * (QAll_B - 1.0f)), 0.0f);
            float tqB = (SAll_B - sqrtf(DB)) * 0.0078125f;
            tauB = fmaxf(mB - 1.0f, fminf(tqB, mB - 0.0078125f));
        }

        // ---- packed Newton via moments: per elem only T += t|t|, Sb += |t| ----
#pragma unroll 1
        for (int it = 0; it < NIT; it++) {
            unsigned long long nA2, nB2;
            unsigned long long TA2 = 0, SbA2 = 0, TB2 = 0, SbB2 = 0;
            float ntA = -tauA, ntB = -tauB;
            PACK2(nA2, ntA, ntA);
            PACK2(nB2, ntB, ntB);
#pragma unroll
            for (int t = 0; t < 16; t++) {
                unsigned long long t2, a2;
                ADD2(t2, zA[t], nA2);
                a2 = t2 & ABSM;
                FMA2ACC(TA2, t2, a2);
                ADD2(SbA2, SbA2, a2);
                ADD2(t2, zB[t], nB2);
                a2 = t2 & ABSM;
                FMA2ACC(TB2, t2, a2);
                ADD2(SbB2, SbB2, a2);
            }
            float x0, x1;
            UNPK2(x0, x1, TA2);  float TA  = x0 + x1;
            UNPK2(x0, x1, SbA2); float SbA = x0 + x1;
            UNPK2(x0, x1, TB2);  float TB  = x0 + x1;
            UNPK2(x0, x1, SbB2); float SbB = x0 + x1;
            TA  += __shfl_xor_sync(0xffffffffu, TA, 1);
            TA  += __shfl_xor_sync(0xffffffffu, TA, 2);
            SbA += __shfl_xor_sync(0xffffffffu, SbA, 1);
            SbA += __shfl_xor_sync(0xffffffffu, SbA, 2);
            TB  += __shfl_xor_sync(0xffffffffu, TB, 1);
            TB  += __shfl_xor_sync(0xffffffffu, TB, 2);
            SbB += __shfl_xor_sync(0xffffffffu, SbB, 1);
            SbB += __shfl_xor_sync(0xffffffffu, SbB, 2);
            float sA = fmaf(-128.0f, tauA, SAll_A) + SbA;
            float qA = 2.0f * fmaf(fmaf(128.0f, tauA, -2.0f * SAll_A), tauA, QAll_A) + 2.0f * TA;
            float sB = fmaf(-128.0f, tauB, SAll_B) + SbB;
            float qB = 2.0f * fmaf(fmaf(128.0f, tauB, -2.0f * SAll_B), tauB, QAll_B) + 2.0f * TB;
            tauA += __fdividef(qA - 4.0f, 4.0f * sA);
            tauB += __fdividef(qB - 4.0f, 4.0f * sB);
        }

        // ---- final p = r'^2 (scale cancels), psum, inv ----
        float invA, invB;
        {
            unsigned long long nA2, nB2, pA2 = 0ULL, pB2 = 0ULL;
            float ntA = -tauA, ntB = -tauB;
            PACK2(nA2, ntA, ntA);
            PACK2(nB2, ntB, ntB);
#pragma unroll
            for (int t = 0; t < 16; t++) {
                unsigned long long t2, r2, p2;
                ADD2(t2, zA[t], nA2);
                r2 = t2 & ABSM;
                ADD2(r2, t2, r2);
                MUL2(p2, r2, r2);
                zA[t] = p2;
                ADD2(pA2, pA2, p2);
                ADD2(t2, zB[t], nB2);
                r2 = t2 & ABSM;
                ADD2(r2, t2, r2);
                MUL2(p2, r2, r2);
                zB[t] = p2;
                ADD2(pB2, pB2, p2);
            }
            float p0, p1;
            UNPK2(p0, p1, pA2); float psA = p0 + p1;
            UNPK2(p0, p1, pB2); float psB = p0 + p1;
            psA += __shfl_xor_sync(0xffffffffu, psA, 1);
            psA += __shfl_xor_sync(0xffffffffu, psA, 2);
            psB += __shfl_xor_sync(0xffffffffu, psB, 1);
            psB += __shfl_xor_sync(0xffffffffu, psB, 2);
            invA = __fdividef(1.0f, psA);
            invB = __fdividef(1.0f, psB);
        }

        // ---- warp-local transpose + store, chunk 0 (rows mw..mw+7, zA) ----
#pragma unroll
        for (int t = 0; t < 16; t++) {
            float f0, f1;
            UNPK2(f0, f1, zA[t]);
            *(float2*)(wbuf + g * 132 + t * 8 + 2 * tg) = make_float2(f0 * invA, f1 * invA);
        }
        __syncwarp();
#pragma unroll
        for (int r8 = 0; r8 < 8; r8++) {
            const int row = mw + r8;                 // 0..127
            float4 a = *(const float4*)(wbuf + r8 * 132 + lane * 4);
            float4 v = V4[(hp * 128 + row) * 32 + lane];
            const int kk = hp * 2 + (row >> 6), o = row & 63;
            float4 w;
            w.x = a.x * v.x; w.y = a.y * v.y; w.z = a.z * v.z; w.w = a.w * v.w;
            O4[(((size_t)b * KH + kk) * O_ + o) * 32 + lane] = w;
        }
        __syncwarp();

        // ---- chunk 1 (rows mw+8..mw+15, zB) ----
#pragma unroll
        for (int t = 0; t < 16; t++) {
            float f0, f1;
            UNPK2(f0, f1, zB[t]);
            *(float2*)(wbuf + g * 132 + t * 8 + 2 * tg) = make_float2(f0 * invB, f1 * invB);
        }
        __syncwarp();
#pragma unroll
        for (int r8 = 0; r8 < 8; r8++) {
            const int row = mw + 8 + r8;             // 0..127
            float4 a = *(const float4*)(wbuf + r8 * 132 + lane * 4);
            float4 v = V4[(hp * 128 + row) * 32 + lane];
            const int kk = hp * 2 + (row >> 6), o = row & 63;
            float4 w;
            w.x = a.x * v.x; w.y = a.y * v.y; w.z = a.z * v.z; w.w = a.w * v.w;
            O4[(((size_t)b * KH + kk) * O_ + o) * 32 + lane] = w;
        }
        __syncwarp();
    }
}

// ---------------------------------------------------------------------------
extern "C" void kernel_launch(void* const* d_in, const int* in_sizes, int n_in,
                              void* d_out, int out_size) {
    const float* x = (const float*)d_in[0];   // [2048,128,128]
    const float* w = (const float*)d_in[1];   // [8,128,64]
    const float* q = (const float*)d_in[2];   // [8,64,64]
    const float* v = (const float*)d_in[3];   // [8,64,128]
    float* out = (float*)d_out;               // [2048,8,64,128]

    cudaFuncSetAttribute(main_kernel, cudaFuncAttributeMaxDynamicSharedMemorySize, SM_TOTAL);

    prep_kernel<<<256, 256>>>(w, q);
    main_kernel<<<B_, 256, SM_TOTAL>>>(x, v, out);
}